// round 10
// baseline (speedup 1.0000x reference)
#include <cuda_runtime.h>
#include <cuda_bf16.h>
#include <math.h>
#include <stdint.h>

// ---------------- problem dims ----------------
#define B_   128
#define S_   512
#define D_   256
#define H_   512
#define E_   256
#define V_   1002
#define T_   34
#define G3H  1536   // 3*H

// ---------------- device scratch ----------------
__device__ float g_GI [100663296];              // 65536 * 1536
__device__ float g_Yd1[2228224];                // 4352 * 512 (fp32, for pooling)
__device__ float g_hA [2 * 65536];
__device__ float g_hB [2 * 65536];
__device__ float g_hC [2 * 65536];
__device__ float g_hD [2 * 65536];
__device__ float g_pooled[65536];
__device__ float g_F1 [327680];
__device__ float g_F2 [131072];
__device__ float g_F3 [131072];
__device__ float g_rowloss[128];
__device__ int   g_ctr[8];
__device__ __nv_bfloat16 g_Acat[100663296];     // A in (hi|lo|hi) cat form
__device__ __nv_bfloat16 g_Wcat[8388608];       // W in (hi|hi|lo) cat form
__device__ __nv_bfloat16 g_hcat[262144];        // [2][128][1024] h in (hi|lo) cat form

// ================= common PTX helpers =================
__device__ __forceinline__ uint32_t smem_u32(const void* p) {
    uint32_t a;
    asm("{ .reg .u64 t; cvta.to.shared.u64 t, %1; cvt.u32.u64 %0, t; }" : "=r"(a) : "l"(p));
    return a;
}
__device__ __forceinline__ void mma16816(float* c, const uint32_t* a, const uint32_t* b)
{
    asm volatile(
        "mma.sync.aligned.m16n8k16.row.col.f32.bf16.bf16.f32 "
        "{%0,%1,%2,%3}, {%4,%5,%6,%7}, {%8,%9}, {%0,%1,%2,%3};"
        : "+f"(c[0]), "+f"(c[1]), "+f"(c[2]), "+f"(c[3])
        : "r"(a[0]), "r"(a[1]), "r"(a[2]), "r"(a[3]), "r"(b[0]), "r"(b[1]));
}
__device__ __forceinline__ void ldmx4(uint32_t* r, uint32_t addr)
{
    asm volatile("ldmatrix.sync.aligned.m8n8.x4.shared.b16 {%0,%1,%2,%3}, [%4];"
        : "=r"(r[0]), "=r"(r[1]), "=r"(r[2]), "=r"(r[3]) : "r"(addr));
}
__device__ __forceinline__ void cp16(uint32_t dst, const void* src)
{
    asm volatile("cp.async.cg.shared.global [%0], [%1], 16;" :: "r"(dst), "l"(src));
}
#define CP_COMMIT() asm volatile("cp.async.commit_group;" ::: "memory")
#define CP_WAIT1()  asm volatile("cp.async.wait_group 1;" ::: "memory")
#define CP_WAIT2()  asm volatile("cp.async.wait_group 2;" ::: "memory")

// ================= fp32 -> bf16 split converters =================
__global__ void conv_A(const float* __restrict__ A, __nv_bfloat16* __restrict__ Ac,
                       int K, long total)
{
    long idx = (long)blockIdx.x * 256 + threadIdx.x;
    if (idx >= total) return;
    int row = (int)(idx / K);
    int col = (int)(idx % K);
    float x = A[idx];
    __nv_bfloat16 hi = __float2bfloat16(x);
    __nv_bfloat16 lo = __float2bfloat16(x - __bfloat162float(hi));
    long base = (long)row * 3 * K;
    Ac[base + col]         = hi;
    Ac[base + K + col]     = lo;
    Ac[base + 2 * K + col] = hi;
}

__global__ void conv_W(const float* __restrict__ W, __nv_bfloat16* __restrict__ Wc,
                       int K, int Nreal, long total)
{
    long idx = (long)blockIdx.x * 256 + threadIdx.x;
    if (idx >= total) return;
    int n = (int)(idx / K);
    int c = (int)(idx % K);
    float x = (n < Nreal) ? W[(long)n * K + c] : 0.f;
    __nv_bfloat16 hi = __float2bfloat16(x);
    __nv_bfloat16 lo = __float2bfloat16(x - __bfloat162float(hi));
    long base = (long)n * 3 * K;
    Wc[base + c]         = hi;
    Wc[base + K + c]     = hi;
    Wc[base + 2 * K + c] = lo;
}

__global__ void conv_h0cat(const float* __restrict__ h0, __nv_bfloat16* __restrict__ hcat)
{
    int idx = blockIdx.x * 256 + threadIdx.x;    // 65536
    int b = idx >> 9, col = idx & 511;
    float v = h0[idx];
    __nv_bfloat16 hi = __float2bfloat16(v);
    __nv_bfloat16 lo = __float2bfloat16(v - __bfloat162float(hi));
    hcat[b * 1024 + col]       = hi;
    hcat[b * 1024 + 512 + col] = lo;
}

// ================= mma.sync bf16 GEMM (R8-proven) =================
#define STAGES    3
#define MMG_SAW   72
#define MMG_TILE  (128 * MMG_SAW)
#define MMG_SMEM  (STAGES * 2 * MMG_TILE * 2)

__global__ __launch_bounds__(256) void mma_gemm(
    const __nv_bfloat16* __restrict__ A, const __nv_bfloat16* __restrict__ Wc,
    const float* __restrict__ bias, float* __restrict__ C,
    int Kext, int Nreal, int ldC)
{
    extern __shared__ __nv_bfloat16 sm[];
    const uint32_t suA = smem_u32(sm);
    const uint32_t suB = suA + STAGES * MMG_TILE * 2;

    const int tid  = threadIdx.x;
    const int wid  = tid >> 5;
    const int lane = tid & 31;
    const int g    = lane >> 2;
    const int t    = lane & 3;
    const int wm   = (wid & 3) * 32;
    const int wn   = (wid >> 2) * 64;
    const int m0   = blockIdx.y * 128;
    const int n0   = blockIdx.x * 128;

    const int aoff = (wm + (lane & 15)) * MMG_SAW + (lane >> 4) * 8;
    const int boff = (wn + (lane & 15)) * MMG_SAW + (lane >> 4) * 8;

    float acc[2][8][4];
    #pragma unroll
    for (int i = 0; i < 2; i++)
        #pragma unroll
        for (int j = 0; j < 8; j++)
            #pragma unroll
            for (int q = 0; q < 4; q++) acc[i][j][q] = 0.f;

    const int nk = Kext >> 6;

    #pragma unroll
    for (int s = 0; s < STAGES - 1; s++) {
        if (s < nk) {
            const int k0 = s << 6;
            const uint32_t dA = suA + s * (MMG_TILE * 2);
            const uint32_t dB = suB + s * (MMG_TILE * 2);
            #pragma unroll
            for (int i = 0; i < 4; i++) {
                int f = i * 256 + tid;
                int r = f >> 3, u = (f & 7) * 8;
                cp16(dA + (uint32_t)(r * MMG_SAW + u) * 2, A  + (long)(m0 + r) * Kext + k0 + u);
                cp16(dB + (uint32_t)(r * MMG_SAW + u) * 2, Wc + (long)(n0 + r) * Kext + k0 + u);
            }
        }
        CP_COMMIT();
    }

    for (int kc = 0; kc < nk; kc++) {
        {
            const int kl = kc + STAGES - 1;
            if (kl < nk) {
                const int k0 = kl << 6;
                const int bfi = kl % STAGES;
                const uint32_t dA = suA + bfi * (MMG_TILE * 2);
                const uint32_t dB = suB + bfi * (MMG_TILE * 2);
                #pragma unroll
                for (int i = 0; i < 4; i++) {
                    int f = i * 256 + tid;
                    int r = f >> 3, u = (f & 7) * 8;
                    cp16(dA + (uint32_t)(r * MMG_SAW + u) * 2, A  + (long)(m0 + r) * Kext + k0 + u);
                    cp16(dB + (uint32_t)(r * MMG_SAW + u) * 2, Wc + (long)(n0 + r) * Kext + k0 + u);
                }
            }
            CP_COMMIT();
        }
        CP_WAIT2();
        __syncthreads();

        const int p = kc % STAGES;
        const uint32_t bA = suA + p * (MMG_TILE * 2);
        const uint32_t bB = suB + p * (MMG_TILE * 2);

        #pragma unroll
        for (int ks = 0; ks < 4; ks++) {
            uint32_t af[2][4], bf[4][4];
            #pragma unroll
            for (int i = 0; i < 2; i++)
                ldmx4(af[i], bA + 2u * (uint32_t)(aoff + i * 16 * MMG_SAW + ks * 16));
            #pragma unroll
            for (int j = 0; j < 4; j++)
                ldmx4(bf[j], bB + 2u * (uint32_t)(boff + j * 16 * MMG_SAW + ks * 16));
            #pragma unroll
            for (int i = 0; i < 2; i++)
                #pragma unroll
                for (int jj = 0; jj < 8; jj++) {
                    uint32_t b2[2] = { bf[jj >> 1][jj & 1], bf[jj >> 1][(jj & 1) + 2] };
                    mma16816(acc[i][jj], af[i], b2);
                }
        }
        __syncthreads();
    }

    #pragma unroll
    for (int i = 0; i < 2; i++) {
        #pragma unroll
        for (int j = 0; j < 8; j++) {
            int col = n0 + wn + j * 8 + 2 * t;
            if (col >= Nreal) continue;
            float b0 = bias[col], b1 = bias[col + 1];
            int row0 = m0 + wm + i * 16 + g;
            float2 v0 = make_float2(acc[i][j][0] + b0, acc[i][j][1] + b1);
            float2 v1 = make_float2(acc[i][j][2] + b0, acc[i][j][3] + b1);
            *(float2*)(C + (long)row0 * ldC + col)       = v0;
            *(float2*)(C + (long)(row0 + 8) * ldC + col) = v1;
        }
    }
}

// ================= persistent tensor-core GRU layer =================
// grid = 64 CTAs: bid = mhalf*32 + nt. nt -> 16 h-cols (48 gh-rows); mhalf -> 64 batch rows.
// Whh split resident in smem [12 chunks][48][136] laid out (hi|hi|lo) to pair with the
// h stream (hi|lo|hi-re-read): products hi*hi + lo*hi + hi*lo. Warp tile 16(M) x 24(N).
#define RSAW   136
#define RW_CH  (48 * RSAW)                  // 6528 elems / chunk
#define RH_CH  (64 * RSAW)                  // 8704 elems / buf
#define OFF_H  (12 * RW_CH * 2)             // 156672
#define OFF_GH (OFF_H + 3 * RH_CH * 2)      // 208896
#define SMEM_MMA (OFF_GH + 64 * 48 * 4)     // 221184

__global__ __launch_bounds__(256) void gru_layer_mma(
    const float* __restrict__ gi_base, long gi_bstride,
    const float* __restrict__ Whh, const float* __restrict__ bhh,
    const float* __restrict__ h0,
    float* __restrict__ hbuf,
    __nv_bfloat16* __restrict__ hcat,       // [2][128*1024], slot 0 prefilled with h0cat
    float* __restrict__ y_out, long y_bstride, long y_tstride,
    __nv_bfloat16* __restrict__ ycat,       // optional (hi|lo|hi) rows, row = b*nsteps+t
    int nsteps, int* counters)
{
    extern __shared__ char smx[];
    __nv_bfloat16* sW = (__nv_bfloat16*)smx;
    float* sGH = (float*)(smx + OFF_GH);
    const uint32_t suW = smem_u32(smx);
    const uint32_t suH = suW + OFF_H;

    const int tid  = threadIdx.x;
    const int wid  = tid >> 5;
    const int lane = tid & 31;
    const int g    = lane >> 2;
    const int tq   = lane & 3;
    const int bid  = blockIdx.x;
    const int nt    = bid & 31;
    const int mhalf = bid >> 5;
    const int hcolBase = nt * 16;
    const int rowBase  = mhalf * 64;
    const int wm = (wid & 3) * 16;
    const int wn = (wid >> 2) * 24;

    // ---- build resident Whh split: (hi | hi | lo) across the 12 K-chunks ----
    for (int i = tid; i < 48 * 512; i += 256) {
        int c = i >> 9, k = i & 511;
        int gate = c >> 4, hc = c & 15;
        float v = Whh[(long)(gate * 512 + hcolBase + hc) * 512 + k];
        __nv_bfloat16 hi = __float2bfloat16(v);
        __nv_bfloat16 lo = __float2bfloat16(v - __bfloat162float(hi));
        int ch = k >> 7, off = k & 127;
        sW[(ch    ) * RW_CH + c * RSAW + off] = hi;   // pairs h_hi
        sW[(ch + 4) * RW_CH + c * RSAW + off] = hi;   // pairs h_lo
        sW[(ch + 8) * RW_CH + c * RSAW + off] = lo;   // pairs h_hi (re-read)
    }
    __syncthreads();

    int* ctr = counters + mhalf;

    for (int t = 0; t < nsteps; t++) {
        const __nv_bfloat16* hcs = hcat + (t & 1) * 131072;
        __nv_bfloat16* hcd = hcat + ((t + 1) & 1) * 131072;
        const float* hp = (t == 0) ? h0 : (hbuf + (long)(t & 1) * 65536);
        float* ho = hbuf + (long)((t + 1) & 1) * 65536;
        const float* gi_t = gi_base + (long)t * G3H;

        float acc[3][4];
        #pragma unroll
        for (int j = 0; j < 3; j++)
            #pragma unroll
            for (int q = 0; q < 4; q++) acc[j][q] = 0.f;

        // prologue: issue chunks 0,1
        #pragma unroll
        for (int s = 0; s < 2; s++) {
            const int sk0 = s * 128;    // chunks 0,1 are in seg0
            const uint32_t dst = suH + s * (RH_CH * 2);
            #pragma unroll
            for (int i = 0; i < 4; i++) {
                int f = i * 256 + tid;
                int r = f >> 4, u = f & 15;
                cp16(dst + (uint32_t)(r * RSAW + u * 8) * 2,
                     hcs + (long)(rowBase + r) * 1024 + sk0 + u * 8);
            }
            CP_COMMIT();
        }

        for (int c = 0; c < 12; c++) {
            CP_WAIT1();
            __syncthreads();
            if (c + 2 < 12) {
                const int cl = c + 2;
                const int sk0 = ((cl < 8) ? cl : (cl - 8)) * 128;
                const uint32_t dst = suH + (cl % 3) * (RH_CH * 2);
                #pragma unroll
                for (int i = 0; i < 4; i++) {
                    int f = i * 256 + tid;
                    int r = f >> 4, u = f & 15;
                    cp16(dst + (uint32_t)(r * RSAW + u * 8) * 2,
                         hcs + (long)(rowBase + r) * 1024 + sk0 + u * 8);
                }
            }
            CP_COMMIT();

            const uint32_t bA = suH + (c % 3) * (RH_CH * 2);
            const uint32_t bW = suW + (uint32_t)c * (RW_CH * 2);
            #pragma unroll
            for (int ks = 0; ks < 8; ks++) {
                uint32_t af[4], b0[4], b1[4];
                ldmx4(af, bA + 2u * (uint32_t)((wm + (lane & 15)) * RSAW + (lane >> 4) * 8 + ks * 16));
                ldmx4(b0, bW + 2u * (uint32_t)((wn +     (lane & 15)) * RSAW + (lane >> 4) * 8 + ks * 16));
                ldmx4(b1, bW + 2u * (uint32_t)((wn + 8 + (lane & 15)) * RSAW + (lane >> 4) * 8 + ks * 16));
                uint32_t f0[2] = { b0[0], b0[2] };
                uint32_t f1[2] = { b0[1], b0[3] };
                uint32_t f2[2] = { b1[1], b1[3] };
                mma16816(acc[0], af, f0);
                mma16816(acc[1], af, f1);
                mma16816(acc[2], af, f2);
            }
        }

        // write gh tile to smem
        #pragma unroll
        for (int j = 0; j < 3; j++) {
            int col = wn + j * 8 + 2 * tq;
            *(float2*)(sGH + (wm + g) * 48 + col)     = make_float2(acc[j][0], acc[j][1]);
            *(float2*)(sGH + (wm + g + 8) * 48 + col) = make_float2(acc[j][2], acc[j][3]);
        }
        __syncthreads();

        // gate fusion: 64 rows x 16 h-cols, 4 per thread
        #pragma unroll
        for (int q = 0; q < 4; q++) {
            int o   = q * 256 + tid;
            int row = o >> 4;
            int hc  = o & 15;
            int b   = rowBase + row;
            int col = hcolBase + hc;
            float ghr = sGH[row * 48 + hc]      + bhh[col];
            float ghz = sGH[row * 48 + 16 + hc] + bhh[512 + col];
            float ghn = sGH[row * 48 + 32 + hc] + bhh[1024 + col];
            const float* gi = gi_t + (long)b * gi_bstride;
            float r  = 1.f / (1.f + expf(-(gi[col] + ghr)));
            float z  = 1.f / (1.f + expf(-(gi[512 + col] + ghz)));
            float n  = tanhf(gi[1024 + col] + r * ghn);
            float hpv = __ldcg(hp + (long)b * 512 + col);
            float hn = (1.f - z) * n + z * hpv;
            ho[(long)b * 512 + col] = hn;
            __nv_bfloat16 hi = __float2bfloat16(hn);
            __nv_bfloat16 lo = __float2bfloat16(hn - __bfloat162float(hi));
            hcd[(long)b * 1024 + col]       = hi;
            hcd[(long)b * 1024 + 512 + col] = lo;
            if (y_out)
                y_out[(long)b * y_bstride + (long)t * y_tstride + col] = hn;
            if (ycat) {
                __nv_bfloat16* yr = ycat + ((long)b * nsteps + t) * 1536;
                yr[col]        = hi;
                yr[512 + col]  = lo;
                yr[1024 + col] = hi;
            }
        }

        // grid barrier per M-half (32 CTAs, co-resident)
        __syncthreads();
        if (tid == 0) {
            __threadfence();
            atomicAdd(ctr, 1);
            int target = 32 * (t + 1);
            volatile int* vc = ctr;
            while (*vc < target) { __nanosleep(32); }
            __threadfence();
        }
        __syncthreads();
    }
}

// ================= small kernels =================
__global__ void gather_emb_cat(const int* __restrict__ ids, const float* __restrict__ emb,
                               __nv_bfloat16* __restrict__ tg)
{
    int m = blockIdx.x;
    int t = threadIdx.x;
    int id = ids[m];
    float x = emb[(long)id * E_ + t];
    __nv_bfloat16 hi = __float2bfloat16(x);
    __nv_bfloat16 lo = __float2bfloat16(x - __bfloat162float(hi));
    __nv_bfloat16* dst = tg + (long)m * (3 * E_);
    dst[t]           = hi;
    dst[E_ + t]      = lo;
    dst[2 * E_ + t]  = hi;
}

__global__ void pool_kernel(const float* __restrict__ y, const int* __restrict__ lengths,
                            float* __restrict__ pooled)
{
    int idx = blockIdx.x * blockDim.x + threadIdx.x;
    int b = idx >> 9, h = idx & 511;
    int L = lengths[b];
    float s = 0.f;
    for (int t = 0; t < L; t++) s += y[((long)b * T_ + t) * H_ + h];
    pooled[idx] = s;
}

__global__ void rowloss_kernel(const float* __restrict__ x, float* __restrict__ rowloss,
                               int ld)
{
    __shared__ float sh[V_];
    __shared__ float red[256];
    int b = blockIdx.x;
    int t = threadIdx.x;

    float mx = -1e30f;
    for (int v = t; v < V_; v += 256) {
        float s = 1.f / (1.f + expf(-x[(long)b * ld + v]));
        sh[v] = s;
        mx = fmaxf(mx, s);
    }
    red[t] = mx; __syncthreads();
    for (int o = 128; o > 0; o >>= 1) {
        if (t < o) red[t] = fmaxf(red[t], red[t + o]);
        __syncthreads();
    }
    mx = red[0];
    __syncthreads();

    float sum = 0.f;
    for (int v = t; v < V_; v += 256) sum += expf(sh[v] - mx);
    red[t] = sum; __syncthreads();
    for (int o = 128; o > 0; o >>= 1) {
        if (t < o) red[t] += red[t + o];
        __syncthreads();
    }
    if (t == 0) rowloss[b] = (mx + logf(red[0])) - sh[V_ - 1];
}

__global__ void finalize_kernel(const float* __restrict__ rowloss, float* __restrict__ out)
{
    __shared__ float red[128];
    int t = threadIdx.x;
    red[t] = rowloss[t]; __syncthreads();
    for (int o = 64; o > 0; o >>= 1) {
        if (t < o) red[t] += red[t + o];
        __syncthreads();
    }
    if (t == 0) out[0] = red[0] / 128.f;
}

// ================= host =================
static __nv_bfloat16 *s_Acat, *s_Wcat, *s_hcat;

static void gemm_full(const float* A, const float* W, const float* bias, float* C,
                      int M, int Nreal, int Npad, int K, int ldC)
{
    long ta = (long)M * K;
    conv_A<<<(unsigned)((ta + 255) / 256), 256>>>(A, s_Acat, K, ta);
    long tw = (long)Npad * K;
    conv_W<<<(unsigned)((tw + 255) / 256), 256>>>(W, s_Wcat, K, Nreal, tw);
    dim3 grid(Npad / 128, M / 128);
    mma_gemm<<<grid, 256, MMG_SMEM>>>(s_Acat, s_Wcat, bias, C, 3 * K, Nreal, ldC);
}

static void gemm_precat(const __nv_bfloat16* Acat, const float* W, const float* bias,
                        float* C, int M, int Nreal, int Npad, int K, int ldC)
{
    long tw = (long)Npad * K;
    conv_W<<<(unsigned)((tw + 255) / 256), 256>>>(W, s_Wcat, K, Nreal, tw);
    dim3 grid(Npad / 128, M / 128);
    mma_gemm<<<grid, 256, MMG_SMEM>>>(Acat, s_Wcat, bias, C, 3 * K, Nreal, ldC);
}

extern "C" void kernel_launch(void* const* d_in, const int* in_sizes, int n_in,
                              void* d_out, int out_size)
{
    const float* source    = (const float*)d_in[0];
    const int*   tgt_ids   = (const int*)  d_in[1];
    const int*   lengths   = (const int*)  d_in[2];
    const float* emb       = (const float*)d_in[3];
    const float* eWih0 = (const float*)d_in[4],  *eWhh0 = (const float*)d_in[5];
    const float* ebih0 = (const float*)d_in[6],  *ebhh0 = (const float*)d_in[7];
    const float* eWih1 = (const float*)d_in[8],  *eWhh1 = (const float*)d_in[9];
    const float* ebih1 = (const float*)d_in[10], *ebhh1 = (const float*)d_in[11];
    const float* dWih0 = (const float*)d_in[12], *dWhh0 = (const float*)d_in[13];
    const float* dbih0 = (const float*)d_in[14], *dbhh0 = (const float*)d_in[15];
    const float* dWih1 = (const float*)d_in[16], *dWhh1 = (const float*)d_in[17];
    const float* dbih1 = (const float*)d_in[18], *dbhh1 = (const float*)d_in[19];
    const float* fcW1 = (const float*)d_in[20], *fcb1 = (const float*)d_in[21];
    const float* fcW2 = (const float*)d_in[22], *fcb2 = (const float*)d_in[23];
    const float* fcW3 = (const float*)d_in[24], *fcb3 = (const float*)d_in[25];
    float* out = (float*)d_out;

    float *GI, *Yd1, *hA, *hB, *hC, *hD, *pooled, *F1, *F2, *F3, *rl;
    int* ctr;
    cudaGetSymbolAddress((void**)&GI,  g_GI);
    cudaGetSymbolAddress((void**)&Yd1, g_Yd1);
    cudaGetSymbolAddress((void**)&hA,  g_hA);
    cudaGetSymbolAddress((void**)&hB,  g_hB);
    cudaGetSymbolAddress((void**)&hC,  g_hC);
    cudaGetSymbolAddress((void**)&hD,  g_hD);
    cudaGetSymbolAddress((void**)&pooled, g_pooled);
    cudaGetSymbolAddress((void**)&F1,  g_F1);
    cudaGetSymbolAddress((void**)&F2,  g_F2);
    cudaGetSymbolAddress((void**)&F3,  g_F3);
    cudaGetSymbolAddress((void**)&rl,  g_rowloss);
    cudaGetSymbolAddress((void**)&ctr, g_ctr);
    cudaGetSymbolAddress((void**)&s_Acat, g_Acat);
    cudaGetSymbolAddress((void**)&s_Wcat, g_Wcat);
    cudaGetSymbolAddress((void**)&s_hcat, g_hcat);

    cudaFuncSetAttribute(mma_gemm,
                         cudaFuncAttributeMaxDynamicSharedMemorySize, MMG_SMEM);
    cudaFuncSetAttribute(gru_layer_mma,
                         cudaFuncAttributeMaxDynamicSharedMemorySize, SMEM_MMA);

    cudaMemsetAsync(hA, 0, 65536 * sizeof(float), 0);
    cudaMemsetAsync(hB, 0, 65536 * sizeof(float), 0);
    cudaMemsetAsync(ctr, 0, 8 * sizeof(int), 0);
    cudaMemsetAsync(s_hcat, 0, 131072 * sizeof(__nv_bfloat16), 0);  // hcat slot 0 = zeros

    // ---- encoder layer 0 ----
    gemm_full(source, eWih0, ebih0, GI, B_ * S_, G3H, G3H, D_, G3H);
    gru_layer_mma<<<64, 256, SMEM_MMA>>>(
        GI, (long)S_ * G3H, eWhh0, ebhh0,
        hA, hA, s_hcat, (float*)0, 0, 0, s_Acat /*Y0 cat*/, S_, ctr + 0);

    // ---- encoder layer 1 ----
    gemm_precat(s_Acat, eWih1, ebih1, GI, B_ * S_, G3H, G3H, H_, G3H);
    cudaMemsetAsync(s_hcat, 0, 131072 * sizeof(__nv_bfloat16), 0);
    gru_layer_mma<<<64, 256, SMEM_MMA>>>(
        GI, (long)S_ * G3H, eWhh1, ebhh1,
        hB, hB, s_hcat, (float*)0, 0, 0, (__nv_bfloat16*)0, S_, ctr + 2);

    // ---- decoder layer 0 ----
    gather_emb_cat<<<B_ * T_, 256>>>(tgt_ids, emb, s_Acat);
    gemm_precat(s_Acat, dWih0, dbih0, GI, B_ * T_, G3H, G3H, E_, G3H);
    conv_h0cat<<<256, 256>>>(hA, s_hcat);          // h0 = enc L0 final (slot 0)
    gru_layer_mma<<<64, 256, SMEM_MMA>>>(
        GI, (long)T_ * G3H, dWhh0, dbhh0,
        hA, hC, s_hcat, (float*)0, 0, 0, s_Acat /*Yd0 cat*/, T_, ctr + 4);

    // ---- decoder layer 1 ----
    gemm_precat(s_Acat, dWih1, dbih1, GI, B_ * T_, G3H, G3H, H_, G3H);
    conv_h0cat<<<256, 256>>>(hB, s_hcat);          // h0 = enc L1 final (slot 0)
    gru_layer_mma<<<64, 256, SMEM_MMA>>>(
        GI, (long)T_ * G3H, dWhh1, dbhh1,
        hB, hD, s_hcat, Yd1, (long)T_ * H_, (long)H_, (__nv_bfloat16*)0, T_, ctr + 6);

    // ---- pool + FC head + loss ----
    pool_kernel<<<256, 256>>>(Yd1, lengths, pooled);
    gemm_full(pooled, fcW1, fcb1, F1, B_, 5 * H_, 5 * H_, H_,     5 * H_);
    gemm_full(F1,     fcW2, fcb2, F2, B_, 2 * H_, 2 * H_, 5 * H_, 2 * H_);
    gemm_full(F2,     fcW3, fcb3, F3, B_, V_,     1024,   2 * H_, 1024);
    rowloss_kernel<<<B_, 256>>>(F3, rl, 1024);
    finalize_kernel<<<1, 128>>>(rl, out);
}

// round 11
// speedup vs baseline: 1.5945x; 1.5945x over previous
#include <cuda_runtime.h>
#include <cuda_bf16.h>
#include <math.h>
#include <stdint.h>

// ---------------- problem dims ----------------
#define B_   128
#define S_   512
#define D_   256
#define H_   512
#define E_   256
#define V_   1002
#define T_   34
#define G3H  1536   // 3*H

// ---------------- device scratch ----------------
__device__ float g_GI [100663296];              // 65536 * 1536
__device__ float g_Yd1[2228224];                // 4352 * 512 (fp32, for pooling)
__device__ float g_hA [2 * 65536];
__device__ float g_hB [2 * 65536];
__device__ float g_hC [2 * 65536];
__device__ float g_hD [2 * 65536];
__device__ float g_pooled[65536];
__device__ float g_F1 [327680];
__device__ float g_F2 [131072];
__device__ float g_F3 [131072];
__device__ float g_rowloss[128];
__device__ int   g_ctr[16];
__device__ __nv_bfloat16 g_Acat[100663296];     // A in (hi|lo|hi) cat form
__device__ __nv_bfloat16 g_Wcat[8388608];       // W in (hi|hi|lo) cat form
__device__ __nv_bfloat16 g_hcat[262144];        // [2][128][1024] h in (hi|lo) cat form

// ================= common PTX helpers =================
__device__ __forceinline__ uint32_t smem_u32(const void* p) {
    uint32_t a;
    asm("{ .reg .u64 t; cvta.to.shared.u64 t, %1; cvt.u32.u64 %0, t; }" : "=r"(a) : "l"(p));
    return a;
}
__device__ __forceinline__ void mma16816(float* c, const uint32_t* a, const uint32_t* b)
{
    asm volatile(
        "mma.sync.aligned.m16n8k16.row.col.f32.bf16.bf16.f32 "
        "{%0,%1,%2,%3}, {%4,%5,%6,%7}, {%8,%9}, {%0,%1,%2,%3};"
        : "+f"(c[0]), "+f"(c[1]), "+f"(c[2]), "+f"(c[3])
        : "r"(a[0]), "r"(a[1]), "r"(a[2]), "r"(a[3]), "r"(b[0]), "r"(b[1]));
}
__device__ __forceinline__ void ldmx4(uint32_t* r, uint32_t addr)
{
    asm volatile("ldmatrix.sync.aligned.m8n8.x4.shared.b16 {%0,%1,%2,%3}, [%4];"
        : "=r"(r[0]), "=r"(r[1]), "=r"(r[2]), "=r"(r[3]) : "r"(addr));
}
__device__ __forceinline__ void cp16(uint32_t dst, const void* src)
{
    asm volatile("cp.async.cg.shared.global [%0], [%1], 16;" :: "r"(dst), "l"(src));
}
#define CP_COMMIT() asm volatile("cp.async.commit_group;" ::: "memory")
#define CP_WAIT0()  asm volatile("cp.async.wait_group 0;" ::: "memory")
#define CP_WAIT2()  asm volatile("cp.async.wait_group 2;" ::: "memory")

// ================= fp32 -> bf16 split converters =================
__global__ void conv_A(const float* __restrict__ A, __nv_bfloat16* __restrict__ Ac,
                       int K, long total)
{
    long idx = (long)blockIdx.x * 256 + threadIdx.x;
    if (idx >= total) return;
    int row = (int)(idx / K);
    int col = (int)(idx % K);
    float x = A[idx];
    __nv_bfloat16 hi = __float2bfloat16(x);
    __nv_bfloat16 lo = __float2bfloat16(x - __bfloat162float(hi));
    long base = (long)row * 3 * K;
    Ac[base + col]         = hi;
    Ac[base + K + col]     = lo;
    Ac[base + 2 * K + col] = hi;
}

__global__ void conv_W(const float* __restrict__ W, __nv_bfloat16* __restrict__ Wc,
                       int K, int Nreal, long total)
{
    long idx = (long)blockIdx.x * 256 + threadIdx.x;
    if (idx >= total) return;
    int n = (int)(idx / K);
    int c = (int)(idx % K);
    float x = (n < Nreal) ? W[(long)n * K + c] : 0.f;
    __nv_bfloat16 hi = __float2bfloat16(x);
    __nv_bfloat16 lo = __float2bfloat16(x - __bfloat162float(hi));
    long base = (long)n * 3 * K;
    Wc[base + c]         = hi;
    Wc[base + K + c]     = hi;
    Wc[base + 2 * K + c] = lo;
}

__global__ void conv_h0cat(const float* __restrict__ h0, __nv_bfloat16* __restrict__ hcat)
{
    int idx = blockIdx.x * 256 + threadIdx.x;    // 65536
    int b = idx >> 9, col = idx & 511;
    float v = h0[idx];
    __nv_bfloat16 hi = __float2bfloat16(v);
    __nv_bfloat16 lo = __float2bfloat16(v - __bfloat162float(hi));
    hcat[b * 1024 + col]       = hi;
    hcat[b * 1024 + 512 + col] = lo;
}

// ================= mma.sync bf16 GEMM (R8-proven) =================
#define STAGES    3
#define MMG_SAW   72
#define MMG_TILE  (128 * MMG_SAW)
#define MMG_SMEM  (STAGES * 2 * MMG_TILE * 2)

__global__ __launch_bounds__(256) void mma_gemm(
    const __nv_bfloat16* __restrict__ A, const __nv_bfloat16* __restrict__ Wc,
    const float* __restrict__ bias, float* __restrict__ C,
    int Kext, int Nreal, int ldC)
{
    extern __shared__ __nv_bfloat16 sm[];
    const uint32_t suA = smem_u32(sm);
    const uint32_t suB = suA + STAGES * MMG_TILE * 2;

    const int tid  = threadIdx.x;
    const int wid  = tid >> 5;
    const int lane = tid & 31;
    const int g    = lane >> 2;
    const int t    = lane & 3;
    const int wm   = (wid & 3) * 32;
    const int wn   = (wid >> 2) * 64;
    const int m0   = blockIdx.y * 128;
    const int n0   = blockIdx.x * 128;

    const int aoff = (wm + (lane & 15)) * MMG_SAW + (lane >> 4) * 8;
    const int boff = (wn + (lane & 15)) * MMG_SAW + (lane >> 4) * 8;

    float acc[2][8][4];
    #pragma unroll
    for (int i = 0; i < 2; i++)
        #pragma unroll
        for (int j = 0; j < 8; j++)
            #pragma unroll
            for (int q = 0; q < 4; q++) acc[i][j][q] = 0.f;

    const int nk = Kext >> 6;

    #pragma unroll
    for (int s = 0; s < STAGES - 1; s++) {
        if (s < nk) {
            const int k0 = s << 6;
            const uint32_t dA = suA + s * (MMG_TILE * 2);
            const uint32_t dB = suB + s * (MMG_TILE * 2);
            #pragma unroll
            for (int i = 0; i < 4; i++) {
                int f = i * 256 + tid;
                int r = f >> 3, u = (f & 7) * 8;
                cp16(dA + (uint32_t)(r * MMG_SAW + u) * 2, A  + (long)(m0 + r) * Kext + k0 + u);
                cp16(dB + (uint32_t)(r * MMG_SAW + u) * 2, Wc + (long)(n0 + r) * Kext + k0 + u);
            }
        }
        CP_COMMIT();
    }

    for (int kc = 0; kc < nk; kc++) {
        {
            const int kl = kc + STAGES - 1;
            if (kl < nk) {
                const int k0 = kl << 6;
                const int bfi = kl % STAGES;
                const uint32_t dA = suA + bfi * (MMG_TILE * 2);
                const uint32_t dB = suB + bfi * (MMG_TILE * 2);
                #pragma unroll
                for (int i = 0; i < 4; i++) {
                    int f = i * 256 + tid;
                    int r = f >> 3, u = (f & 7) * 8;
                    cp16(dA + (uint32_t)(r * MMG_SAW + u) * 2, A  + (long)(m0 + r) * Kext + k0 + u);
                    cp16(dB + (uint32_t)(r * MMG_SAW + u) * 2, Wc + (long)(n0 + r) * Kext + k0 + u);
                }
            }
            CP_COMMIT();
        }
        CP_WAIT2();
        __syncthreads();

        const int p = kc % STAGES;
        const uint32_t bA = suA + p * (MMG_TILE * 2);
        const uint32_t bB = suB + p * (MMG_TILE * 2);

        #pragma unroll
        for (int ks = 0; ks < 4; ks++) {
            uint32_t af[2][4], bf[4][4];
            #pragma unroll
            for (int i = 0; i < 2; i++)
                ldmx4(af[i], bA + 2u * (uint32_t)(aoff + i * 16 * MMG_SAW + ks * 16));
            #pragma unroll
            for (int j = 0; j < 4; j++)
                ldmx4(bf[j], bB + 2u * (uint32_t)(boff + j * 16 * MMG_SAW + ks * 16));
            #pragma unroll
            for (int i = 0; i < 2; i++)
                #pragma unroll
                for (int jj = 0; jj < 8; jj++) {
                    uint32_t b2[2] = { bf[jj >> 1][jj & 1], bf[jj >> 1][(jj & 1) + 2] };
                    mma16816(acc[i][jj], af[i], b2);
                }
        }
        __syncthreads();
    }

    #pragma unroll
    for (int i = 0; i < 2; i++) {
        #pragma unroll
        for (int j = 0; j < 8; j++) {
            int col = n0 + wn + j * 8 + 2 * t;
            if (col >= Nreal) continue;
            float b0 = bias[col], b1 = bias[col + 1];
            int row0 = m0 + wm + i * 16 + g;
            float2 v0 = make_float2(acc[i][j][0] + b0, acc[i][j][1] + b1);
            float2 v1 = make_float2(acc[i][j][2] + b0, acc[i][j][3] + b1);
            *(float2*)(C + (long)row0 * ldC + col)       = v0;
            *(float2*)(C + (long)(row0 + 8) * ldC + col) = v1;
        }
    }
}

// ================= persistent tensor-core GRU layer, v2 =================
// grid = 128 CTAs: bid = mq*32 + nt. mq -> 32 batch rows, nt -> 16 h-cols (48 gh-rows).
// W resident dedup'd: w_hi chunks 0-3, w_lo chunks 4-7 (104KB). Full h slice (hi+lo,
// 8 chunks, 70KB) loaded once per step; 12 chunk-MMAs run back-to-back with no syncs.
// K split across 2 warp groups (each warp m16 x n24 x 6 chunks); partials summed in fusion.
#define R2_SAW  136
#define R2_WCH  (48 * R2_SAW)                   // 6528 elems per W chunk
#define R2_HCH  (32 * R2_SAW)                   // 4352 elems per h chunk
#define R2_OFFH  (8 * R2_WCH * 2)               // 104448 B
#define R2_OFFGH (R2_OFFH + 8 * R2_HCH * 2)     // 174080 B
#define R2_SMEM  (R2_OFFGH + 2 * 32 * 48 * 4)   // 186368 B

__global__ __launch_bounds__(256) void gru_layer_mma2(
    const float* __restrict__ gi_base, long gi_bstride,
    const float* __restrict__ Whh, const float* __restrict__ bhh,
    const float* __restrict__ h0,
    float* __restrict__ hbuf,
    __nv_bfloat16* __restrict__ hcat,       // [2][128*1024], slot 0 prefilled
    float* __restrict__ y_out, long y_bstride, long y_tstride,
    __nv_bfloat16* __restrict__ ycat,       // optional (hi|lo|hi) rows, row = b*nsteps+t
    int nsteps, int* counters)              // counters[4], pre-zeroed
{
    extern __shared__ char smx[];
    __nv_bfloat16* sW = (__nv_bfloat16*)smx;
    float* sGH = (float*)(smx + R2_OFFGH);
    const uint32_t suW = smem_u32(smx);
    const uint32_t suH = suW + R2_OFFH;

    const int tid  = threadIdx.x;
    const int wid  = tid >> 5;
    const int lane = tid & 31;
    const int g    = lane >> 2;
    const int tq   = lane & 3;
    const int nt   = blockIdx.x & 31;
    const int mq   = blockIdx.x >> 5;
    const int hcolBase = nt * 16;
    const int rowBase  = mq * 32;
    const int wm = (wid & 1) * 16;          // M block
    const int wn = ((wid >> 1) & 1) * 24;   // N half
    const int kg = wid >> 2;                // K group: chunks [kg*6, kg*6+6)

    // ---- build resident Whh split: w_hi chunks 0-3, w_lo chunks 4-7 ----
    for (int i = tid; i < 48 * 512; i += 256) {
        int c = i >> 9, k = i & 511;
        int gate = c >> 4, hc = c & 15;
        float v = Whh[(long)(gate * 512 + hcolBase + hc) * 512 + k];
        __nv_bfloat16 hi = __float2bfloat16(v);
        __nv_bfloat16 lo = __float2bfloat16(v - __bfloat162float(hi));
        int ch = k >> 7, off = k & 127;
        sW[ch * R2_WCH + c * R2_SAW + off]       = hi;
        sW[(ch + 4) * R2_WCH + c * R2_SAW + off] = lo;
    }
    __syncthreads();

    int* ctr = counters + mq;

    for (int t = 0; t < nsteps; t++) {
        const __nv_bfloat16* hcs = hcat + (t & 1) * 131072;
        __nv_bfloat16* hcd = hcat + ((t + 1) & 1) * 131072;
        const float* hp = (t == 0) ? h0 : (hbuf + (long)(t & 1) * 65536);
        float* ho = hbuf + (long)((t + 1) & 1) * 65536;
        const float* gi_t = gi_base + (long)t * G3H;

        // ---- load full h slice (hi+lo = 8 chunks) in one shot: 4096 cp16 ----
        #pragma unroll
        for (int i = 0; i < 16; i++) {
            int f = i * 256 + tid;
            int r = f >> 7;                  // 0..31 (batch row within quarter)
            int q = f & 127;                 // 16B block within 1024-col cat row
            int seg = q >> 6;                // 0 = hi, 1 = lo
            int qq  = q & 63;
            int hb  = seg * 4 + (qq >> 4);   // buffer 0..7
            int off8 = (qq & 15) * 8;
            cp16(suH + (uint32_t)(hb * R2_HCH + r * R2_SAW + off8) * 2,
                 hcs + (long)(rowBase + r) * 1024 + q * 8);
        }
        CP_COMMIT();
        CP_WAIT0();
        __syncthreads();

        float acc[3][4];
        #pragma unroll
        for (int j = 0; j < 3; j++)
            #pragma unroll
            for (int q = 0; q < 4; q++) acc[j][q] = 0.f;

        // ---- 6 chunk-MMAs for this warp's K group, no intervening syncs ----
        #pragma unroll
        for (int cc = 0; cc < 6; cc++) {
            const int c  = kg * 6 + cc;
            const int wb = (c < 4) ? c : c - 4;      // w_hi,w_hi,w_lo pairing
            const int hb = (c < 8) ? c : c - 8;      // h_hi,h_lo,h_hi pairing
            const uint32_t bA = suH + (uint32_t)hb * (R2_HCH * 2);
            const uint32_t bW = suW + (uint32_t)wb * (R2_WCH * 2);
            #pragma unroll
            for (int ks = 0; ks < 8; ks++) {
                uint32_t af[4], b0[4], b1[4];
                ldmx4(af, bA + 2u * (uint32_t)((wm + (lane & 15)) * R2_SAW + (lane >> 4) * 8 + ks * 16));
                ldmx4(b0, bW + 2u * (uint32_t)((wn +     (lane & 15)) * R2_SAW + (lane >> 4) * 8 + ks * 16));
                ldmx4(b1, bW + 2u * (uint32_t)((wn + 8 + (lane & 15)) * R2_SAW + (lane >> 4) * 8 + ks * 16));
                uint32_t f0[2] = { b0[0], b0[2] };
                uint32_t f1[2] = { b0[1], b0[3] };
                uint32_t f2[2] = { b1[1], b1[3] };
                mma16816(acc[0], af, f0);
                mma16816(acc[1], af, f1);
                mma16816(acc[2], af, f2);
            }
        }

        // ---- write K-group partial gh tiles ----
        {
            float* dst = sGH + kg * (32 * 48);
            #pragma unroll
            for (int j = 0; j < 3; j++) {
                int col = wn + j * 8 + 2 * tq;
                *(float2*)(dst + (wm + g) * 48 + col)     = make_float2(acc[j][0], acc[j][1]);
                *(float2*)(dst + (wm + g + 8) * 48 + col) = make_float2(acc[j][2], acc[j][3]);
            }
        }
        __syncthreads();

        // ---- gate fusion: 32 rows x 16 h-cols, 2 per thread ----
        #pragma unroll
        for (int q2 = 0; q2 < 2; q2++) {
            int o   = q2 * 256 + tid;
            int row = o >> 4;
            int hc  = o & 15;
            int b   = rowBase + row;
            int col = hcolBase + hc;
            float ghr = sGH[row * 48 + hc]      + sGH[1536 + row * 48 + hc]      + bhh[col];
            float ghz = sGH[row * 48 + 16 + hc] + sGH[1536 + row * 48 + 16 + hc] + bhh[512 + col];
            float ghn = sGH[row * 48 + 32 + hc] + sGH[1536 + row * 48 + 32 + hc] + bhh[1024 + col];
            const float* gi = gi_t + (long)b * gi_bstride;
            float r  = 1.f / (1.f + expf(-(gi[col] + ghr)));
            float z  = 1.f / (1.f + expf(-(gi[512 + col] + ghz)));
            float n  = tanhf(gi[1024 + col] + r * ghn);
            float hpv = __ldcg(hp + (long)b * 512 + col);
            float hn = (1.f - z) * n + z * hpv;
            ho[(long)b * 512 + col] = hn;
            __nv_bfloat16 hi = __float2bfloat16(hn);
            __nv_bfloat16 lo = __float2bfloat16(hn - __bfloat162float(hi));
            hcd[(long)b * 1024 + col]       = hi;
            hcd[(long)b * 1024 + 512 + col] = lo;
            if (y_out)
                y_out[(long)b * y_bstride + (long)t * y_tstride + col] = hn;
            if (ycat) {
                __nv_bfloat16* yr = ycat + ((long)b * nsteps + t) * 1536;
                yr[col]        = hi;
                yr[512 + col]  = lo;
                yr[1024 + col] = hi;
            }
        }

        // ---- grid barrier per batch quarter (32 CTAs, co-resident) ----
        __syncthreads();
        if (tid == 0) {
            __threadfence();
            atomicAdd(ctr, 1);
            int target = 32 * (t + 1);
            volatile int* vc = ctr;
            while (*vc < target) { __nanosleep(32); }
            __threadfence();
        }
        __syncthreads();
    }
}

// ================= small kernels =================
__global__ void gather_emb_cat(const int* __restrict__ ids, const float* __restrict__ emb,
                               __nv_bfloat16* __restrict__ tg)
{
    int m = blockIdx.x;
    int t = threadIdx.x;
    int id = ids[m];
    float x = emb[(long)id * E_ + t];
    __nv_bfloat16 hi = __float2bfloat16(x);
    __nv_bfloat16 lo = __float2bfloat16(x - __bfloat162float(hi));
    __nv_bfloat16* dst = tg + (long)m * (3 * E_);
    dst[t]           = hi;
    dst[E_ + t]      = lo;
    dst[2 * E_ + t]  = hi;
}

__global__ void pool_kernel(const float* __restrict__ y, const int* __restrict__ lengths,
                            float* __restrict__ pooled)
{
    int idx = blockIdx.x * blockDim.x + threadIdx.x;
    int b = idx >> 9, h = idx & 511;
    int L = lengths[b];
    float s = 0.f;
    for (int t = 0; t < L; t++) s += y[((long)b * T_ + t) * H_ + h];
    pooled[idx] = s;
}

__global__ void rowloss_kernel(const float* __restrict__ x, float* __restrict__ rowloss,
                               int ld)
{
    __shared__ float sh[V_];
    __shared__ float red[256];
    int b = blockIdx.x;
    int t = threadIdx.x;

    float mx = -1e30f;
    for (int v = t; v < V_; v += 256) {
        float s = 1.f / (1.f + expf(-x[(long)b * ld + v]));
        sh[v] = s;
        mx = fmaxf(mx, s);
    }
    red[t] = mx; __syncthreads();
    for (int o = 128; o > 0; o >>= 1) {
        if (t < o) red[t] = fmaxf(red[t], red[t + o]);
        __syncthreads();
    }
    mx = red[0];
    __syncthreads();

    float sum = 0.f;
    for (int v = t; v < V_; v += 256) sum += expf(sh[v] - mx);
    red[t] = sum; __syncthreads();
    for (int o = 128; o > 0; o >>= 1) {
        if (t < o) red[t] += red[t + o];
        __syncthreads();
    }
    if (t == 0) rowloss[b] = (mx + logf(red[0])) - sh[V_ - 1];
}

__global__ void finalize_kernel(const float* __restrict__ rowloss, float* __restrict__ out)
{
    __shared__ float red[128];
    int t = threadIdx.x;
    red[t] = rowloss[t]; __syncthreads();
    for (int o = 64; o > 0; o >>= 1) {
        if (t < o) red[t] += red[t + o];
        __syncthreads();
    }
    if (t == 0) out[0] = red[0] / 128.f;
}

// ================= host =================
static __nv_bfloat16 *s_Acat, *s_Wcat, *s_hcat;

static void gemm_full(const float* A, const float* W, const float* bias, float* C,
                      int M, int Nreal, int Npad, int K, int ldC)
{
    long ta = (long)M * K;
    conv_A<<<(unsigned)((ta + 255) / 256), 256>>>(A, s_Acat, K, ta);
    long tw = (long)Npad * K;
    conv_W<<<(unsigned)((tw + 255) / 256), 256>>>(W, s_Wcat, K, Nreal, tw);
    dim3 grid(Npad / 128, M / 128);
    mma_gemm<<<grid, 256, MMG_SMEM>>>(s_Acat, s_Wcat, bias, C, 3 * K, Nreal, ldC);
}

static void gemm_precat(const __nv_bfloat16* Acat, const float* W, const float* bias,
                        float* C, int M, int Nreal, int Npad, int K, int ldC)
{
    long tw = (long)Npad * K;
    conv_W<<<(unsigned)((tw + 255) / 256), 256>>>(W, s_Wcat, K, Nreal, tw);
    dim3 grid(Npad / 128, M / 128);
    mma_gemm<<<grid, 256, MMG_SMEM>>>(Acat, s_Wcat, bias, C, 3 * K, Nreal, ldC);
}

extern "C" void kernel_launch(void* const* d_in, const int* in_sizes, int n_in,
                              void* d_out, int out_size)
{
    const float* source    = (const float*)d_in[0];
    const int*   tgt_ids   = (const int*)  d_in[1];
    const int*   lengths   = (const int*)  d_in[2];
    const float* emb       = (const float*)d_in[3];
    const float* eWih0 = (const float*)d_in[4],  *eWhh0 = (const float*)d_in[5];
    const float* ebih0 = (const float*)d_in[6],  *ebhh0 = (const float*)d_in[7];
    const float* eWih1 = (const float*)d_in[8],  *eWhh1 = (const float*)d_in[9];
    const float* ebih1 = (const float*)d_in[10], *ebhh1 = (const float*)d_in[11];
    const float* dWih0 = (const float*)d_in[12], *dWhh0 = (const float*)d_in[13];
    const float* dbih0 = (const float*)d_in[14], *dbhh0 = (const float*)d_in[15];
    const float* dWih1 = (const float*)d_in[16], *dWhh1 = (const float*)d_in[17];
    const float* dbih1 = (const float*)d_in[18], *dbhh1 = (const float*)d_in[19];
    const float* fcW1 = (const float*)d_in[20], *fcb1 = (const float*)d_in[21];
    const float* fcW2 = (const float*)d_in[22], *fcb2 = (const float*)d_in[23];
    const float* fcW3 = (const float*)d_in[24], *fcb3 = (const float*)d_in[25];
    float* out = (float*)d_out;

    float *GI, *Yd1, *hA, *hB, *hC, *hD, *pooled, *F1, *F2, *F3, *rl;
    int* ctr;
    cudaGetSymbolAddress((void**)&GI,  g_GI);
    cudaGetSymbolAddress((void**)&Yd1, g_Yd1);
    cudaGetSymbolAddress((void**)&hA,  g_hA);
    cudaGetSymbolAddress((void**)&hB,  g_hB);
    cudaGetSymbolAddress((void**)&hC,  g_hC);
    cudaGetSymbolAddress((void**)&hD,  g_hD);
    cudaGetSymbolAddress((void**)&pooled, g_pooled);
    cudaGetSymbolAddress((void**)&F1,  g_F1);
    cudaGetSymbolAddress((void**)&F2,  g_F2);
    cudaGetSymbolAddress((void**)&F3,  g_F3);
    cudaGetSymbolAddress((void**)&rl,  g_rowloss);
    cudaGetSymbolAddress((void**)&ctr, g_ctr);
    cudaGetSymbolAddress((void**)&s_Acat, g_Acat);
    cudaGetSymbolAddress((void**)&s_Wcat, g_Wcat);
    cudaGetSymbolAddress((void**)&s_hcat, g_hcat);

    cudaFuncSetAttribute(mma_gemm,
                         cudaFuncAttributeMaxDynamicSharedMemorySize, MMG_SMEM);
    cudaFuncSetAttribute(gru_layer_mma2,
                         cudaFuncAttributeMaxDynamicSharedMemorySize, R2_SMEM);

    cudaMemsetAsync(hA, 0, 65536 * sizeof(float), 0);
    cudaMemsetAsync(hB, 0, 65536 * sizeof(float), 0);
    cudaMemsetAsync(ctr, 0, 16 * sizeof(int), 0);
    cudaMemsetAsync(s_hcat, 0, 131072 * sizeof(__nv_bfloat16), 0);  // hcat slot 0 = zeros

    // ---- encoder layer 0 ----
    gemm_full(source, eWih0, ebih0, GI, B_ * S_, G3H, G3H, D_, G3H);
    gru_layer_mma2<<<128, 256, R2_SMEM>>>(
        GI, (long)S_ * G3H, eWhh0, ebhh0,
        hA, hA, s_hcat, (float*)0, 0, 0, s_Acat /*Y0 cat*/, S_, ctr + 0);

    // ---- encoder layer 1 ----
    gemm_precat(s_Acat, eWih1, ebih1, GI, B_ * S_, G3H, G3H, H_, G3H);
    cudaMemsetAsync(s_hcat, 0, 131072 * sizeof(__nv_bfloat16), 0);
    gru_layer_mma2<<<128, 256, R2_SMEM>>>(
        GI, (long)S_ * G3H, eWhh1, ebhh1,
        hB, hB, s_hcat, (float*)0, 0, 0, (__nv_bfloat16*)0, S_, ctr + 4);

    // ---- decoder layer 0 ----
    gather_emb_cat<<<B_ * T_, 256>>>(tgt_ids, emb, s_Acat);
    gemm_precat(s_Acat, dWih0, dbih0, GI, B_ * T_, G3H, G3H, E_, G3H);
    conv_h0cat<<<256, 256>>>(hA, s_hcat);          // h0 = enc L0 final (slot 0)
    gru_layer_mma2<<<128, 256, R2_SMEM>>>(
        GI, (long)T_ * G3H, dWhh0, dbhh0,
        hA, hC, s_hcat, (float*)0, 0, 0, s_Acat /*Yd0 cat*/, T_, ctr + 8);

    // ---- decoder layer 1 ----
    gemm_precat(s_Acat, dWih1, dbih1, GI, B_ * T_, G3H, G3H, H_, G3H);
    conv_h0cat<<<256, 256>>>(hB, s_hcat);          // h0 = enc L1 final (slot 0)
    gru_layer_mma2<<<128, 256, R2_SMEM>>>(
        GI, (long)T_ * G3H, dWhh1, dbhh1,
        hB, hD, s_hcat, Yd1, (long)T_ * H_, (long)H_, (__nv_bfloat16*)0, T_, ctr + 12);

    // ---- pool + FC head + loss ----
    pool_kernel<<<256, 256>>>(Yd1, lengths, pooled);
    gemm_full(pooled, fcW1, fcb1, F1, B_, 5 * H_, 5 * H_, H_,     5 * H_);
    gemm_full(F1,     fcW2, fcb2, F2, B_, 2 * H_, 2 * H_, 5 * H_, 2 * H_);
    gemm_full(F2,     fcW3, fcb3, F3, B_, V_,     1024,   2 * H_, 1024);
    rowloss_kernel<<<B_, 256>>>(F3, rl, 1024);
    finalize_kernel<<<1, 128>>>(rl, out);
}

// round 12
// speedup vs baseline: 2.0601x; 1.2920x over previous
#include <cuda_runtime.h>
#include <cuda_bf16.h>
#include <math.h>
#include <stdint.h>

// ---------------- problem dims ----------------
#define B_   128
#define S_   512
#define D_   256
#define H_   512
#define E_   256
#define V_   1002
#define T_   34
#define G3H  1536   // 3*H

// ---------------- device scratch ----------------
__device__ float g_GI [100663296];              // 65536 * 1536
__device__ float g_Yd1[2228224];                // 4352 * 512 (fp32, for pooling)
__device__ float g_hA [2 * 65536];
__device__ float g_hB [2 * 65536];
__device__ float g_hC [2 * 65536];
__device__ float g_hD [2 * 65536];
__device__ float g_pooled[65536];
__device__ float g_F1 [327680];
__device__ float g_F2 [131072];
__device__ float g_F3 [131072];
__device__ float g_rowloss[128];
__device__ int   g_ctr[16];
__device__ __nv_bfloat16 g_Acat[100663296];     // A in (hi|lo|hi) cat form
__device__ __nv_bfloat16 g_Wcat[8388608];       // W in (hi|hi|lo) cat form
__device__ __nv_bfloat16 g_hcat[262144];        // [2][128][1024] h in (hi|lo) cat form

// ================= common PTX helpers =================
__device__ __forceinline__ uint32_t smem_u32(const void* p) {
    uint32_t a;
    asm("{ .reg .u64 t; cvta.to.shared.u64 t, %1; cvt.u32.u64 %0, t; }" : "=r"(a) : "l"(p));
    return a;
}
__device__ __forceinline__ void mma16816(float* c, const uint32_t* a, const uint32_t* b)
{
    asm volatile(
        "mma.sync.aligned.m16n8k16.row.col.f32.bf16.bf16.f32 "
        "{%0,%1,%2,%3}, {%4,%5,%6,%7}, {%8,%9}, {%0,%1,%2,%3};"
        : "+f"(c[0]), "+f"(c[1]), "+f"(c[2]), "+f"(c[3])
        : "r"(a[0]), "r"(a[1]), "r"(a[2]), "r"(a[3]), "r"(b[0]), "r"(b[1]));
}
__device__ __forceinline__ void ldmx4(uint32_t* r, uint32_t addr)
{
    asm volatile("ldmatrix.sync.aligned.m8n8.x4.shared.b16 {%0,%1,%2,%3}, [%4];"
        : "=r"(r[0]), "=r"(r[1]), "=r"(r[2]), "=r"(r[3]) : "r"(addr));
}
__device__ __forceinline__ void cp16(uint32_t dst, const void* src)
{
    asm volatile("cp.async.cg.shared.global [%0], [%1], 16;" :: "r"(dst), "l"(src));
}
#define CP_COMMIT() asm volatile("cp.async.commit_group;" ::: "memory")
#define CP_WAIT0()  asm volatile("cp.async.wait_group 0;" ::: "memory")
#define CP_WAIT1()  asm volatile("cp.async.wait_group 1;" ::: "memory")
#define CP_WAIT2()  asm volatile("cp.async.wait_group 2;" ::: "memory")

// ================= fp32 -> bf16 split converters =================
__global__ void conv_A(const float* __restrict__ A, __nv_bfloat16* __restrict__ Ac,
                       int K, long total)
{
    long idx = (long)blockIdx.x * 256 + threadIdx.x;
    if (idx >= total) return;
    int row = (int)(idx / K);
    int col = (int)(idx % K);
    float x = A[idx];
    __nv_bfloat16 hi = __float2bfloat16(x);
    __nv_bfloat16 lo = __float2bfloat16(x - __bfloat162float(hi));
    long base = (long)row * 3 * K;
    Ac[base + col]         = hi;
    Ac[base + K + col]     = lo;
    Ac[base + 2 * K + col] = hi;
}

__global__ void conv_W(const float* __restrict__ W, __nv_bfloat16* __restrict__ Wc,
                       int K, int Nreal, long total)
{
    long idx = (long)blockIdx.x * 256 + threadIdx.x;
    if (idx >= total) return;
    int n = (int)(idx / K);
    int c = (int)(idx % K);
    float x = (n < Nreal) ? W[(long)n * K + c] : 0.f;
    __nv_bfloat16 hi = __float2bfloat16(x);
    __nv_bfloat16 lo = __float2bfloat16(x - __bfloat162float(hi));
    long base = (long)n * 3 * K;
    Wc[base + c]         = hi;
    Wc[base + K + c]     = hi;
    Wc[base + 2 * K + c] = lo;
}

__global__ void conv_h0cat(const float* __restrict__ h0, __nv_bfloat16* __restrict__ hcat)
{
    int idx = blockIdx.x * 256 + threadIdx.x;    // 65536
    int b = idx >> 9, col = idx & 511;
    float v = h0[idx];
    __nv_bfloat16 hi = __float2bfloat16(v);
    __nv_bfloat16 lo = __float2bfloat16(v - __bfloat162float(hi));
    hcat[b * 1024 + col]       = hi;
    hcat[b * 1024 + 512 + col] = lo;
}

// ================= mma.sync bf16 GEMM (R8-proven) =================
#define STAGES    3
#define MMG_SAW   72
#define MMG_TILE  (128 * MMG_SAW)
#define MMG_SMEM  (STAGES * 2 * MMG_TILE * 2)

__global__ __launch_bounds__(256) void mma_gemm(
    const __nv_bfloat16* __restrict__ A, const __nv_bfloat16* __restrict__ Wc,
    const float* __restrict__ bias, float* __restrict__ C,
    int Kext, int Nreal, int ldC)
{
    extern __shared__ __nv_bfloat16 sm[];
    const uint32_t suA = smem_u32(sm);
    const uint32_t suB = suA + STAGES * MMG_TILE * 2;

    const int tid  = threadIdx.x;
    const int wid  = tid >> 5;
    const int lane = tid & 31;
    const int g    = lane >> 2;
    const int t    = lane & 3;
    const int wm   = (wid & 3) * 32;
    const int wn   = (wid >> 2) * 64;
    const int m0   = blockIdx.y * 128;
    const int n0   = blockIdx.x * 128;

    const int aoff = (wm + (lane & 15)) * MMG_SAW + (lane >> 4) * 8;
    const int boff = (wn + (lane & 15)) * MMG_SAW + (lane >> 4) * 8;

    float acc[2][8][4];
    #pragma unroll
    for (int i = 0; i < 2; i++)
        #pragma unroll
        for (int j = 0; j < 8; j++)
            #pragma unroll
            for (int q = 0; q < 4; q++) acc[i][j][q] = 0.f;

    const int nk = Kext >> 6;

    #pragma unroll
    for (int s = 0; s < STAGES - 1; s++) {
        if (s < nk) {
            const int k0 = s << 6;
            const uint32_t dA = suA + s * (MMG_TILE * 2);
            const uint32_t dB = suB + s * (MMG_TILE * 2);
            #pragma unroll
            for (int i = 0; i < 4; i++) {
                int f = i * 256 + tid;
                int r = f >> 3, u = (f & 7) * 8;
                cp16(dA + (uint32_t)(r * MMG_SAW + u) * 2, A  + (long)(m0 + r) * Kext + k0 + u);
                cp16(dB + (uint32_t)(r * MMG_SAW + u) * 2, Wc + (long)(n0 + r) * Kext + k0 + u);
            }
        }
        CP_COMMIT();
    }

    for (int kc = 0; kc < nk; kc++) {
        {
            const int kl = kc + STAGES - 1;
            if (kl < nk) {
                const int k0 = kl << 6;
                const int bfi = kl % STAGES;
                const uint32_t dA = suA + bfi * (MMG_TILE * 2);
                const uint32_t dB = suB + bfi * (MMG_TILE * 2);
                #pragma unroll
                for (int i = 0; i < 4; i++) {
                    int f = i * 256 + tid;
                    int r = f >> 3, u = (f & 7) * 8;
                    cp16(dA + (uint32_t)(r * MMG_SAW + u) * 2, A  + (long)(m0 + r) * Kext + k0 + u);
                    cp16(dB + (uint32_t)(r * MMG_SAW + u) * 2, Wc + (long)(n0 + r) * Kext + k0 + u);
                }
            }
            CP_COMMIT();
        }
        CP_WAIT2();
        __syncthreads();

        const int p = kc % STAGES;
        const uint32_t bA = suA + p * (MMG_TILE * 2);
        const uint32_t bB = suB + p * (MMG_TILE * 2);

        #pragma unroll
        for (int ks = 0; ks < 4; ks++) {
            uint32_t af[2][4], bf[4][4];
            #pragma unroll
            for (int i = 0; i < 2; i++)
                ldmx4(af[i], bA + 2u * (uint32_t)(aoff + i * 16 * MMG_SAW + ks * 16));
            #pragma unroll
            for (int j = 0; j < 4; j++)
                ldmx4(bf[j], bB + 2u * (uint32_t)(boff + j * 16 * MMG_SAW + ks * 16));
            #pragma unroll
            for (int i = 0; i < 2; i++)
                #pragma unroll
                for (int jj = 0; jj < 8; jj++) {
                    uint32_t b2[2] = { bf[jj >> 1][jj & 1], bf[jj >> 1][(jj & 1) + 2] };
                    mma16816(acc[i][jj], af[i], b2);
                }
        }
        __syncthreads();
    }

    #pragma unroll
    for (int i = 0; i < 2; i++) {
        #pragma unroll
        for (int j = 0; j < 8; j++) {
            int col = n0 + wn + j * 8 + 2 * t;
            if (col >= Nreal) continue;
            float b0 = bias[col], b1 = bias[col + 1];
            int row0 = m0 + wm + i * 16 + g;
            float2 v0 = make_float2(acc[i][j][0] + b0, acc[i][j][1] + b1);
            float2 v1 = make_float2(acc[i][j][2] + b0, acc[i][j][3] + b1);
            *(float2*)(C + (long)row0 * ldC + col)       = v0;
            *(float2*)(C + (long)(row0 + 8) * ldC + col) = v1;
        }
    }
}

// ================= persistent tensor-core GRU layer, v3 =================
// v2 + latency hiding: gi prefetched across the barrier, hp/bhh in smem,
// split-wait h load (h_hi group starts MMA while h_lo in flight).
#define R2_SAW  136
#define R2_WCH  (48 * R2_SAW)                   // 6528 elems per W chunk
#define R2_HCH  (32 * R2_SAW)                   // 4352 elems per h chunk
#define R3_OFFH  (8 * R2_WCH * 2)               // 104448
#define R3_OFFGH (R3_OFFH + 8 * R2_HCH * 2)     // 174080
#define R3_OFFGI (R3_OFFGH + 2 * 32 * 48 * 4)   // 186368
#define R3_OFFHP (R3_OFFGI + 32 * 48 * 4)       // 192512
#define R3_OFFBH (R3_OFFHP + 32 * 16 * 4)       // 194560
#define R3_SMEM  (R3_OFFBH + 48 * 4)            // 194752

__global__ __launch_bounds__(256) void gru_layer_mma3(
    const float* __restrict__ gi_base, long gi_bstride,
    const float* __restrict__ Whh, const float* __restrict__ bhh,
    const float* __restrict__ h0,
    float* __restrict__ hbuf,
    __nv_bfloat16* __restrict__ hcat,       // [2][128*1024], slot 0 prefilled
    float* __restrict__ y_out, long y_bstride, long y_tstride,
    __nv_bfloat16* __restrict__ ycat,       // optional (hi|lo|hi) rows, row = b*nsteps+t
    int nsteps, int* counters)
{
    extern __shared__ char smx[];
    __nv_bfloat16* sW = (__nv_bfloat16*)smx;
    float* sGH = (float*)(smx + R3_OFFGH);
    float* sGI = (float*)(smx + R3_OFFGI);
    float* sHP = (float*)(smx + R3_OFFHP);
    float* sBH = (float*)(smx + R3_OFFBH);
    const uint32_t suW  = smem_u32(smx);
    const uint32_t suH  = suW + R3_OFFH;
    const uint32_t suGI = suW + R3_OFFGI;
    const uint32_t suHP = suW + R3_OFFHP;

    const int tid  = threadIdx.x;
    const int wid  = tid >> 5;
    const int lane = tid & 31;
    const int g    = lane >> 2;
    const int tq   = lane & 3;
    const int nt   = blockIdx.x & 31;
    const int mq   = blockIdx.x >> 5;
    const int hcolBase = nt * 16;
    const int rowBase  = mq * 32;
    const int wm = (wid & 1) * 16;          // M block
    const int wn = ((wid >> 1) & 1) * 24;   // N half
    const int kg = wid >> 2;                // K group

    // chunk schedule: phase1 (idx 0..3) = h_hi only; phase2 (idx 4..5) = h_lo
    const int order[2][6] = { {0, 1, 2, 3, 4, 5}, {8, 9, 10, 11, 6, 7} };

    // ---- build resident Whh split + bhh cache ----
    for (int i = tid; i < 48 * 512; i += 256) {
        int c = i >> 9, k = i & 511;
        int gate = c >> 4, hc = c & 15;
        float v = Whh[(long)(gate * 512 + hcolBase + hc) * 512 + k];
        __nv_bfloat16 hi = __float2bfloat16(v);
        __nv_bfloat16 lo = __float2bfloat16(v - __bfloat162float(hi));
        int ch = k >> 7, off = k & 127;
        sW[ch * R2_WCH + c * R2_SAW + off]       = hi;
        sW[(ch + 4) * R2_WCH + c * R2_SAW + off] = lo;
    }
    if (tid < 48)
        sBH[tid] = bhh[(tid >> 4) * 512 + hcolBase + (tid & 15)];
    __syncthreads();

    // ---- prologue: prefetch gi(0) (group GI) ----
    {
        int f = tid;
        if (f < 384) {
            int r = f / 12, rest = f % 12, seg = rest >> 2, q = rest & 3;
            cp16(suGI + (uint32_t)(r * 48 + seg * 16 + q * 4) * 4,
                 gi_base + (long)(rowBase + r) * gi_bstride + seg * 512 + hcolBase + q * 4);
        }
        if (f >= 384 && f < 512) {
            int f2 = f - 384;
            // nothing: keep group small
        }
    }
    {
        int f = 256 + tid;
        if (f < 384) {
            int r = f / 12, rest = f % 12, seg = rest >> 2, q = rest & 3;
            cp16(suGI + (uint32_t)(r * 48 + seg * 16 + q * 4) * 4,
                 gi_base + (long)(rowBase + r) * gi_bstride + seg * 512 + hcolBase + q * 4);
        }
    }
    CP_COMMIT();

    int* ctr = counters + mq;

    for (int t = 0; t < nsteps; t++) {
        const __nv_bfloat16* hcs = hcat + (t & 1) * 131072;
        __nv_bfloat16* hcd = hcat + ((t + 1) & 1) * 131072;
        const float* hp = (t == 0) ? h0 : (hbuf + (long)(t & 1) * 65536);
        float* ho = hbuf + (long)((t + 1) & 1) * 65536;

        // ---- group A: h_hi (4 chunks) + hp tile ----
        #pragma unroll
        for (int i = 0; i < 8; i++) {
            int f = i * 256 + tid;                   // 0..2047
            int r = f >> 6;                          // 0..31
            int qq = f & 63;                         // 16B block within hi seg
            int hb = qq >> 4;                        // buffer 0..3
            int off8 = (qq & 15) * 8;
            cp16(suH + (uint32_t)(hb * R2_HCH + r * R2_SAW + off8) * 2,
                 hcs + (long)(rowBase + r) * 1024 + qq * 8);
        }
        if (tid < 128) {
            int r = tid >> 2, q = tid & 3;
            cp16(suHP + (uint32_t)(r * 16 + q * 4) * 4,
                 hp + (long)(rowBase + r) * 512 + hcolBase + q * 4);
        }
        CP_COMMIT();

        // ---- group B: h_lo (4 chunks) ----
        #pragma unroll
        for (int i = 0; i < 8; i++) {
            int f = i * 256 + tid;
            int r = f >> 6;
            int qq = f & 63;
            int hb = 4 + (qq >> 4);
            int off8 = (qq & 15) * 8;
            cp16(suH + (uint32_t)((hb * R2_HCH + r * R2_SAW + off8)) * 2,
                 hcs + (long)(rowBase + r) * 1024 + 512 + qq * 8);
        }
        CP_COMMIT();

        CP_WAIT1();              // gi(t) + group A complete
        __syncthreads();

        float acc[3][4];
        #pragma unroll
        for (int j = 0; j < 3; j++)
            #pragma unroll
            for (int q = 0; q < 4; q++) acc[j][q] = 0.f;

        // ---- phase 1: 4 h_hi chunks ----
        #pragma unroll
        for (int cc = 0; cc < 4; cc++) {
            const int c  = order[kg][cc];
            const int wb = (c < 4) ? c : c - 4;
            const int hb = (c < 8) ? c : c - 8;
            const uint32_t bA = suH + (uint32_t)hb * (R2_HCH * 2);
            const uint32_t bW = suW + (uint32_t)wb * (R2_WCH * 2);
            #pragma unroll
            for (int ks = 0; ks < 8; ks++) {
                uint32_t af[4], b0[4], b1[4];
                ldmx4(af, bA + 2u * (uint32_t)((wm + (lane & 15)) * R2_SAW + (lane >> 4) * 8 + ks * 16));
                ldmx4(b0, bW + 2u * (uint32_t)((wn +     (lane & 15)) * R2_SAW + (lane >> 4) * 8 + ks * 16));
                ldmx4(b1, bW + 2u * (uint32_t)((wn + 8 + (lane & 15)) * R2_SAW + (lane >> 4) * 8 + ks * 16));
                uint32_t f0[2] = { b0[0], b0[2] };
                uint32_t f1[2] = { b0[1], b0[3] };
                uint32_t f2[2] = { b1[1], b1[3] };
                mma16816(acc[0], af, f0);
                mma16816(acc[1], af, f1);
                mma16816(acc[2], af, f2);
            }
        }

        CP_WAIT0();              // group B complete
        __syncthreads();

        // ---- phase 2: 2 h_lo chunks ----
        #pragma unroll
        for (int cc = 4; cc < 6; cc++) {
            const int c  = order[kg][cc];
            const int wb = (c < 4) ? c : c - 4;
            const int hb = (c < 8) ? c : c - 8;
            const uint32_t bA = suH + (uint32_t)hb * (R2_HCH * 2);
            const uint32_t bW = suW + (uint32_t)wb * (R2_WCH * 2);
            #pragma unroll
            for (int ks = 0; ks < 8; ks++) {
                uint32_t af[4], b0[4], b1[4];
                ldmx4(af, bA + 2u * (uint32_t)((wm + (lane & 15)) * R2_SAW + (lane >> 4) * 8 + ks * 16));
                ldmx4(b0, bW + 2u * (uint32_t)((wn +     (lane & 15)) * R2_SAW + (lane >> 4) * 8 + ks * 16));
                ldmx4(b1, bW + 2u * (uint32_t)((wn + 8 + (lane & 15)) * R2_SAW + (lane >> 4) * 8 + ks * 16));
                uint32_t f0[2] = { b0[0], b0[2] };
                uint32_t f1[2] = { b0[1], b0[3] };
                uint32_t f2[2] = { b1[1], b1[3] };
                mma16816(acc[0], af, f0);
                mma16816(acc[1], af, f1);
                mma16816(acc[2], af, f2);
            }
        }

        // ---- write K-group partial gh tiles ----
        {
            float* dst = sGH + kg * (32 * 48);
            #pragma unroll
            for (int j = 0; j < 3; j++) {
                int col = wn + j * 8 + 2 * tq;
                *(float2*)(dst + (wm + g) * 48 + col)     = make_float2(acc[j][0], acc[j][1]);
                *(float2*)(dst + (wm + g + 8) * 48 + col) = make_float2(acc[j][2], acc[j][3]);
            }
        }
        __syncthreads();

        // ---- gate fusion: all operands from smem ----
        #pragma unroll
        for (int q2 = 0; q2 < 2; q2++) {
            int o   = q2 * 256 + tid;
            int row = o >> 4;
            int hc  = o & 15;
            int b   = rowBase + row;
            int col = hcolBase + hc;
            float ghr = sGH[row * 48 + hc]      + sGH[1536 + row * 48 + hc]      + sBH[hc];
            float ghz = sGH[row * 48 + 16 + hc] + sGH[1536 + row * 48 + 16 + hc] + sBH[16 + hc];
            float ghn = sGH[row * 48 + 32 + hc] + sGH[1536 + row * 48 + 32 + hc] + sBH[32 + hc];
            float gir = sGI[row * 48 + hc];
            float giz = sGI[row * 48 + 16 + hc];
            float gin = sGI[row * 48 + 32 + hc];
            float r  = 1.f / (1.f + expf(-(gir + ghr)));
            float z  = 1.f / (1.f + expf(-(giz + ghz)));
            float n  = tanhf(gin + r * ghn);
            float hpv = sHP[row * 16 + hc];
            float hn = (1.f - z) * n + z * hpv;
            ho[(long)b * 512 + col] = hn;
            __nv_bfloat16 hi = __float2bfloat16(hn);
            __nv_bfloat16 lo = __float2bfloat16(hn - __bfloat162float(hi));
            hcd[(long)b * 1024 + col]       = hi;
            hcd[(long)b * 1024 + 512 + col] = lo;
            if (y_out)
                y_out[(long)b * y_bstride + (long)t * y_tstride + col] = hn;
            if (ycat) {
                __nv_bfloat16* yr = ycat + ((long)b * nsteps + t) * 1536;
                yr[col]        = hi;
                yr[512 + col]  = lo;
                yr[1024 + col] = hi;
            }
        }

        // sGI consumed; safe to prefetch gi(t+1) after this sync
        __syncthreads();
        {
            const int tn = t + 1;
            if (tn < nsteps) {
                const float* gi_n = gi_base + (long)tn * G3H;
                #pragma unroll
                for (int i = 0; i < 2; i++) {
                    int f = i * 256 + tid;
                    if (f < 384) {
                        int r = f / 12, rest = f % 12, seg = rest >> 2, q = rest & 3;
                        cp16(suGI + (uint32_t)(r * 48 + seg * 16 + q * 4) * 4,
                             gi_n + (long)(rowBase + r) * gi_bstride + seg * 512 + hcolBase + q * 4);
                    }
                }
            }
            CP_COMMIT();     // always commit to keep group accounting consistent
        }

        // ---- grid barrier per batch quarter (32 CTAs) ----
        if (tid == 0) {
            __threadfence();
            atomicAdd(ctr, 1);
            int target = 32 * (t + 1);
            volatile int* vc = ctr;
            while (*vc < target) { __nanosleep(32); }
            __threadfence();
        }
        __syncthreads();
    }
}

// ================= small kernels =================
__global__ void gather_emb_cat(const int* __restrict__ ids, const float* __restrict__ emb,
                               __nv_bfloat16* __restrict__ tg)
{
    int m = blockIdx.x;
    int t = threadIdx.x;
    int id = ids[m];
    float x = emb[(long)id * E_ + t];
    __nv_bfloat16 hi = __float2bfloat16(x);
    __nv_bfloat16 lo = __float2bfloat16(x - __bfloat162float(hi));
    __nv_bfloat16* dst = tg + (long)m * (3 * E_);
    dst[t]           = hi;
    dst[E_ + t]      = lo;
    dst[2 * E_ + t]  = hi;
}

__global__ void pool_kernel(const float* __restrict__ y, const int* __restrict__ lengths,
                            float* __restrict__ pooled)
{
    int idx = blockIdx.x * blockDim.x + threadIdx.x;
    int b = idx >> 9, h = idx & 511;
    int L = lengths[b];
    float s = 0.f;
    for (int t = 0; t < L; t++) s += y[((long)b * T_ + t) * H_ + h];
    pooled[idx] = s;
}

__global__ void rowloss_kernel(const float* __restrict__ x, float* __restrict__ rowloss,
                               int ld)
{
    __shared__ float sh[V_];
    __shared__ float red[256];
    int b = blockIdx.x;
    int t = threadIdx.x;

    float mx = -1e30f;
    for (int v = t; v < V_; v += 256) {
        float s = 1.f / (1.f + expf(-x[(long)b * ld + v]));
        sh[v] = s;
        mx = fmaxf(mx, s);
    }
    red[t] = mx; __syncthreads();
    for (int o = 128; o > 0; o >>= 1) {
        if (t < o) red[t] = fmaxf(red[t], red[t + o]);
        __syncthreads();
    }
    mx = red[0];
    __syncthreads();

    float sum = 0.f;
    for (int v = t; v < V_; v += 256) sum += expf(sh[v] - mx);
    red[t] = sum; __syncthreads();
    for (int o = 128; o > 0; o >>= 1) {
        if (t < o) red[t] += red[t + o];
        __syncthreads();
    }
    if (t == 0) rowloss[b] = (mx + logf(red[0])) - sh[V_ - 1];
}

__global__ void finalize_kernel(const float* __restrict__ rowloss, float* __restrict__ out)
{
    __shared__ float red[128];
    int t = threadIdx.x;
    red[t] = rowloss[t]; __syncthreads();
    for (int o = 64; o > 0; o >>= 1) {
        if (t < o) red[t] += red[t + o];
        __syncthreads();
    }
    if (t == 0) out[0] = red[0] / 128.f;
}

// ================= host =================
static __nv_bfloat16 *s_Acat, *s_Wcat, *s_hcat;

static void gemm_full(const float* A, const float* W, const float* bias, float* C,
                      int M, int Nreal, int Npad, int K, int ldC)
{
    long ta = (long)M * K;
    conv_A<<<(unsigned)((ta + 255) / 256), 256>>>(A, s_Acat, K, ta);
    long tw = (long)Npad * K;
    conv_W<<<(unsigned)((tw + 255) / 256), 256>>>(W, s_Wcat, K, Nreal, tw);
    dim3 grid(Npad / 128, M / 128);
    mma_gemm<<<grid, 256, MMG_SMEM>>>(s_Acat, s_Wcat, bias, C, 3 * K, Nreal, ldC);
}

static void gemm_precat(const __nv_bfloat16* Acat, const float* W, const float* bias,
                        float* C, int M, int Nreal, int Npad, int K, int ldC)
{
    long tw = (long)Npad * K;
    conv_W<<<(unsigned)((tw + 255) / 256), 256>>>(W, s_Wcat, K, Nreal, tw);
    dim3 grid(Npad / 128, M / 128);
    mma_gemm<<<grid, 256, MMG_SMEM>>>(Acat, s_Wcat, bias, C, 3 * K, Nreal, ldC);
}

extern "C" void kernel_launch(void* const* d_in, const int* in_sizes, int n_in,
                              void* d_out, int out_size)
{
    const float* source    = (const float*)d_in[0];
    const int*   tgt_ids   = (const int*)  d_in[1];
    const int*   lengths   = (const int*)  d_in[2];
    const float* emb       = (const float*)d_in[3];
    const float* eWih0 = (const float*)d_in[4],  *eWhh0 = (const float*)d_in[5];
    const float* ebih0 = (const float*)d_in[6],  *ebhh0 = (const float*)d_in[7];
    const float* eWih1 = (const float*)d_in[8],  *eWhh1 = (const float*)d_in[9];
    const float* ebih1 = (const float*)d_in[10], *ebhh1 = (const float*)d_in[11];
    const float* dWih0 = (const float*)d_in[12], *dWhh0 = (const float*)d_in[13];
    const float* dbih0 = (const float*)d_in[14], *dbhh0 = (const float*)d_in[15];
    const float* dWih1 = (const float*)d_in[16], *dWhh1 = (const float*)d_in[17];
    const float* dbih1 = (const float*)d_in[18], *dbhh1 = (const float*)d_in[19];
    const float* fcW1 = (const float*)d_in[20], *fcb1 = (const float*)d_in[21];
    const float* fcW2 = (const float*)d_in[22], *fcb2 = (const float*)d_in[23];
    const float* fcW3 = (const float*)d_in[24], *fcb3 = (const float*)d_in[25];
    float* out = (float*)d_out;

    float *GI, *Yd1, *hA, *hB, *hC, *hD, *pooled, *F1, *F2, *F3, *rl;
    int* ctr;
    cudaGetSymbolAddress((void**)&GI,  g_GI);
    cudaGetSymbolAddress((void**)&Yd1, g_Yd1);
    cudaGetSymbolAddress((void**)&hA,  g_hA);
    cudaGetSymbolAddress((void**)&hB,  g_hB);
    cudaGetSymbolAddress((void**)&hC,  g_hC);
    cudaGetSymbolAddress((void**)&hD,  g_hD);
    cudaGetSymbolAddress((void**)&pooled, g_pooled);
    cudaGetSymbolAddress((void**)&F1,  g_F1);
    cudaGetSymbolAddress((void**)&F2,  g_F2);
    cudaGetSymbolAddress((void**)&F3,  g_F3);
    cudaGetSymbolAddress((void**)&rl,  g_rowloss);
    cudaGetSymbolAddress((void**)&ctr, g_ctr);
    cudaGetSymbolAddress((void**)&s_Acat, g_Acat);
    cudaGetSymbolAddress((void**)&s_Wcat, g_Wcat);
    cudaGetSymbolAddress((void**)&s_hcat, g_hcat);

    cudaFuncSetAttribute(mma_gemm,
                         cudaFuncAttributeMaxDynamicSharedMemorySize, MMG_SMEM);
    cudaFuncSetAttribute(gru_layer_mma3,
                         cudaFuncAttributeMaxDynamicSharedMemorySize, R3_SMEM);

    cudaMemsetAsync(hA, 0, 65536 * sizeof(float), 0);
    cudaMemsetAsync(hB, 0, 65536 * sizeof(float), 0);
    cudaMemsetAsync(ctr, 0, 16 * sizeof(int), 0);
    cudaMemsetAsync(s_hcat, 0, 131072 * sizeof(__nv_bfloat16), 0);

    // ---- encoder layer 0 ----
    gemm_full(source, eWih0, ebih0, GI, B_ * S_, G3H, G3H, D_, G3H);
    gru_layer_mma3<<<128, 256, R3_SMEM>>>(
        GI, (long)S_ * G3H, eWhh0, ebhh0,
        hA, hA, s_hcat, (float*)0, 0, 0, s_Acat /*Y0 cat*/, S_, ctr + 0);

    // ---- encoder layer 1 ----
    gemm_precat(s_Acat, eWih1, ebih1, GI, B_ * S_, G3H, G3H, H_, G3H);
    cudaMemsetAsync(s_hcat, 0, 131072 * sizeof(__nv_bfloat16), 0);
    gru_layer_mma3<<<128, 256, R3_SMEM>>>(
        GI, (long)S_ * G3H, eWhh1, ebhh1,
        hB, hB, s_hcat, (float*)0, 0, 0, (__nv_bfloat16*)0, S_, ctr + 4);

    // ---- decoder layer 0 ----
    gather_emb_cat<<<B_ * T_, 256>>>(tgt_ids, emb, s_Acat);
    gemm_precat(s_Acat, dWih0, dbih0, GI, B_ * T_, G3H, G3H, E_, G3H);
    conv_h0cat<<<256, 256>>>(hA, s_hcat);
    gru_layer_mma3<<<128, 256, R3_SMEM>>>(
        GI, (long)T_ * G3H, dWhh0, dbhh0,
        hA, hC, s_hcat, (float*)0, 0, 0, s_Acat /*Yd0 cat*/, T_, ctr + 8);

    // ---- decoder layer 1 ----
    gemm_precat(s_Acat, dWih1, dbih1, GI, B_ * T_, G3H, G3H, H_, G3H);
    conv_h0cat<<<256, 256>>>(hB, s_hcat);
    gru_layer_mma3<<<128, 256, R3_SMEM>>>(
        GI, (long)T_ * G3H, dWhh1, dbhh1,
        hB, hD, s_hcat, Yd1, (long)T_ * H_, (long)H_, (__nv_bfloat16*)0, T_, ctr + 12);

    // ---- pool + FC head + loss ----
    pool_kernel<<<256, 256>>>(Yd1, lengths, pooled);
    gemm_full(pooled, fcW1, fcb1, F1, B_, 5 * H_, 5 * H_, H_,     5 * H_);
    gemm_full(F1,     fcW2, fcb2, F2, B_, 2 * H_, 2 * H_, 5 * H_, 2 * H_);
    gemm_full(F2,     fcW3, fcb3, F3, B_, V_,     1024,   2 * H_, 1024);
    rowloss_kernel<<<B_, 256>>>(F3, rl, 1024);
    finalize_kernel<<<1, 128>>>(rl, out);
}

// round 13
// speedup vs baseline: 2.2254x; 1.0803x over previous
#include <cuda_runtime.h>
#include <cuda_bf16.h>
#include <math.h>
#include <stdint.h>

// ---------------- problem dims ----------------
#define B_   128
#define S_   512
#define D_   256
#define H_   512
#define E_   256
#define V_   1002
#define T_   34
#define G3H  1536   // 3*H

// ---------------- device scratch ----------------
__device__ float g_GI [100663296];              // 65536 * 1536
__device__ float g_Yd1[2228224];                // 4352 * 512 (fp32, for pooling)
__device__ float g_pooled[65536];
__device__ float g_F1 [327680];
__device__ float g_F2 [131072];
__device__ float g_F3 [131072];
__device__ float g_rowloss[128];
__device__ int   g_ctr[16];
__device__ __nv_bfloat16 g_Acat[100663296];     // A in (hi|lo|hi) cat form
__device__ __nv_bfloat16 g_Wcat[8388608];       // W in (hi|hi|lo) cat form
__device__ __nv_bfloat16 g_hcat[1048576];       // 4 layers x [2][128*1024] (hi|lo)

// ================= common PTX helpers =================
__device__ __forceinline__ uint32_t smem_u32(const void* p) {
    uint32_t a;
    asm("{ .reg .u64 t; cvta.to.shared.u64 t, %1; cvt.u32.u64 %0, t; }" : "=r"(a) : "l"(p));
    return a;
}
__device__ __forceinline__ void mma16816(float* c, const uint32_t* a, const uint32_t* b)
{
    asm volatile(
        "mma.sync.aligned.m16n8k16.row.col.f32.bf16.bf16.f32 "
        "{%0,%1,%2,%3}, {%4,%5,%6,%7}, {%8,%9}, {%0,%1,%2,%3};"
        : "+f"(c[0]), "+f"(c[1]), "+f"(c[2]), "+f"(c[3])
        : "r"(a[0]), "r"(a[1]), "r"(a[2]), "r"(a[3]), "r"(b[0]), "r"(b[1]));
}
__device__ __forceinline__ void ldmx4(uint32_t* r, uint32_t addr)
{
    asm volatile("ldmatrix.sync.aligned.m8n8.x4.shared.b16 {%0,%1,%2,%3}, [%4];"
        : "=r"(r[0]), "=r"(r[1]), "=r"(r[2]), "=r"(r[3]) : "r"(addr));
}
__device__ __forceinline__ void cp16(uint32_t dst, const void* src)
{
    asm volatile("cp.async.cg.shared.global [%0], [%1], 16;" :: "r"(dst), "l"(src));
}
#define CP_COMMIT() asm volatile("cp.async.commit_group;" ::: "memory")
#define CP_WAIT0()  asm volatile("cp.async.wait_group 0;" ::: "memory")
#define CP_WAIT1()  asm volatile("cp.async.wait_group 1;" ::: "memory")

// ================= fp32 -> bf16 split converters =================
__global__ void conv_A(const float* __restrict__ A, __nv_bfloat16* __restrict__ Ac,
                       int K, long total)
{
    long idx = (long)blockIdx.x * 256 + threadIdx.x;
    if (idx >= total) return;
    int row = (int)(idx / K);
    int col = (int)(idx % K);
    float x = A[idx];
    __nv_bfloat16 hi = __float2bfloat16(x);
    __nv_bfloat16 lo = __float2bfloat16(x - __bfloat162float(hi));
    long base = (long)row * 3 * K;
    Ac[base + col]         = hi;
    Ac[base + K + col]     = lo;
    Ac[base + 2 * K + col] = hi;
}

__global__ void conv_W(const float* __restrict__ W, __nv_bfloat16* __restrict__ Wc,
                       int K, int Nreal, long total)
{
    long idx = (long)blockIdx.x * 256 + threadIdx.x;
    if (idx >= total) return;
    int n = (int)(idx / K);
    int c = (int)(idx % K);
    float x = (n < Nreal) ? W[(long)n * K + c] : 0.f;
    __nv_bfloat16 hi = __float2bfloat16(x);
    __nv_bfloat16 lo = __float2bfloat16(x - __bfloat162float(hi));
    long base = (long)n * 3 * K;
    Wc[base + c]         = hi;
    Wc[base + K + c]     = hi;
    Wc[base + 2 * K + c] = lo;
}

// ================= mma.sync bf16 GEMM (single-sync mainloop) =================
#define STAGES    3
#define MMG_SAW   72
#define MMG_TILE  (128 * MMG_SAW)
#define MMG_SMEM  (STAGES * 2 * MMG_TILE * 2)

__global__ __launch_bounds__(256) void mma_gemm(
    const __nv_bfloat16* __restrict__ A, const __nv_bfloat16* __restrict__ Wc,
    const float* __restrict__ bias, float* __restrict__ C,
    int Kext, int Nreal, int ldC)
{
    extern __shared__ __nv_bfloat16 sm[];
    const uint32_t suA = smem_u32(sm);
    const uint32_t suB = suA + STAGES * MMG_TILE * 2;

    const int tid  = threadIdx.x;
    const int wid  = tid >> 5;
    const int lane = tid & 31;
    const int g    = lane >> 2;
    const int t    = lane & 3;
    const int wm   = (wid & 3) * 32;
    const int wn   = (wid >> 2) * 64;
    const int m0   = blockIdx.y * 128;
    const int n0   = blockIdx.x * 128;

    const int aoff = (wm + (lane & 15)) * MMG_SAW + (lane >> 4) * 8;
    const int boff = (wn + (lane & 15)) * MMG_SAW + (lane >> 4) * 8;

    float acc[2][8][4];
    #pragma unroll
    for (int i = 0; i < 2; i++)
        #pragma unroll
        for (int j = 0; j < 8; j++)
            #pragma unroll
            for (int q = 0; q < 4; q++) acc[i][j][q] = 0.f;

    const int nk = Kext >> 6;

    #pragma unroll
    for (int s = 0; s < STAGES - 1; s++) {
        if (s < nk) {
            const int k0 = s << 6;
            const uint32_t dA = suA + s * (MMG_TILE * 2);
            const uint32_t dB = suB + s * (MMG_TILE * 2);
            #pragma unroll
            for (int i = 0; i < 4; i++) {
                int f = i * 256 + tid;
                int r = f >> 3, u = (f & 7) * 8;
                cp16(dA + (uint32_t)(r * MMG_SAW + u) * 2, A  + (long)(m0 + r) * Kext + k0 + u);
                cp16(dB + (uint32_t)(r * MMG_SAW + u) * 2, Wc + (long)(n0 + r) * Kext + k0 + u);
            }
        }
        CP_COMMIT();
    }

    for (int kc = 0; kc < nk; kc++) {
        CP_WAIT1();             // stage kc complete (only kc+1 may remain)
        __syncthreads();        // all warps done reading stage kc-1 (buffer (kc+2)%3)

        {
            const int kl = kc + 2;
            if (kl < nk) {
                const int k0 = kl << 6;
                const int bfi = kl % STAGES;
                const uint32_t dA = suA + bfi * (MMG_TILE * 2);
                const uint32_t dB = suB + bfi * (MMG_TILE * 2);
                #pragma unroll
                for (int i = 0; i < 4; i++) {
                    int f = i * 256 + tid;
                    int r = f >> 3, u = (f & 7) * 8;
                    cp16(dA + (uint32_t)(r * MMG_SAW + u) * 2, A  + (long)(m0 + r) * Kext + k0 + u);
                    cp16(dB + (uint32_t)(r * MMG_SAW + u) * 2, Wc + (long)(n0 + r) * Kext + k0 + u);
                }
            }
            CP_COMMIT();
        }

        const int p = kc % STAGES;
        const uint32_t bA = suA + p * (MMG_TILE * 2);
        const uint32_t bB = suB + p * (MMG_TILE * 2);

        #pragma unroll
        for (int ks = 0; ks < 4; ks++) {
            uint32_t af[2][4], bf[4][4];
            #pragma unroll
            for (int i = 0; i < 2; i++)
                ldmx4(af[i], bA + 2u * (uint32_t)(aoff + i * 16 * MMG_SAW + ks * 16));
            #pragma unroll
            for (int j = 0; j < 4; j++)
                ldmx4(bf[j], bB + 2u * (uint32_t)(boff + j * 16 * MMG_SAW + ks * 16));
            #pragma unroll
            for (int i = 0; i < 2; i++)
                #pragma unroll
                for (int jj = 0; jj < 8; jj++) {
                    uint32_t b2[2] = { bf[jj >> 1][jj & 1], bf[jj >> 1][(jj & 1) + 2] };
                    mma16816(acc[i][jj], af[i], b2);
                }
        }
    }

    #pragma unroll
    for (int i = 0; i < 2; i++) {
        #pragma unroll
        for (int j = 0; j < 8; j++) {
            int col = n0 + wn + j * 8 + 2 * t;
            if (col >= Nreal) continue;
            float b0 = bias[col], b1 = bias[col + 1];
            int row0 = m0 + wm + i * 16 + g;
            float2 v0 = make_float2(acc[i][j][0] + b0, acc[i][j][1] + b1);
            float2 v1 = make_float2(acc[i][j][2] + b0, acc[i][j][3] + b1);
            *(float2*)(C + (long)row0 * ldC + col)       = v0;
            *(float2*)(C + (long)(row0 + 8) * ldC + col) = v1;
        }
    }
}

// ================= persistent tensor-core GRU layer, v4 =================
// v3 minus the fp32 h round-trip (hpv = hi+lo from smem); early-arrive barrier
// with release/acquire; deferred ycat/y_out stores overlap the spin.
#define R2_SAW  136
#define R2_WCH  (48 * R2_SAW)
#define R2_HCH  (32 * R2_SAW)
#define R4_OFFH  (8 * R2_WCH * 2)               // 104448
#define R4_OFFGH (R4_OFFH + 8 * R2_HCH * 2)     // 174080
#define R4_OFFGI (R4_OFFGH + 2 * 32 * 48 * 4)   // 186368
#define R4_OFFBH (R4_OFFGI + 32 * 48 * 4)       // 192512
#define R4_SMEM  (R4_OFFBH + 48 * 4)            // 192704

__global__ __launch_bounds__(256) void gru_layer_mma4(
    const float* __restrict__ gi_base, long gi_bstride,
    const float* __restrict__ Whh, const float* __restrict__ bhh,
    __nv_bfloat16* __restrict__ hcat,       // [2][128*1024], slot 0 prefilled (h0)
    float* __restrict__ y_out, long y_bstride, long y_tstride,
    __nv_bfloat16* __restrict__ ycat,       // optional (hi|lo|hi) rows, row = b*nsteps+t
    int nsteps, int* counters)
{
    extern __shared__ char smx[];
    __nv_bfloat16* sW = (__nv_bfloat16*)smx;
    const __nv_bfloat16* sHbf = (const __nv_bfloat16*)(smx + R4_OFFH);
    float* sGH = (float*)(smx + R4_OFFGH);
    float* sGI = (float*)(smx + R4_OFFGI);
    float* sBH = (float*)(smx + R4_OFFBH);
    const uint32_t suW  = smem_u32(smx);
    const uint32_t suH  = suW + R4_OFFH;
    const uint32_t suGI = suW + R4_OFFGI;

    const int tid  = threadIdx.x;
    const int wid  = tid >> 5;
    const int lane = tid & 31;
    const int g    = lane >> 2;
    const int tq   = lane & 3;
    const int nt   = blockIdx.x & 31;
    const int mq   = blockIdx.x >> 5;
    const int hcolBase = nt * 16;
    const int rowBase  = mq * 32;
    const int wm = (wid & 1) * 16;
    const int wn = ((wid >> 1) & 1) * 24;
    const int kg = wid >> 2;

    const int order[2][6] = { {0, 1, 2, 3, 4, 5}, {8, 9, 10, 11, 6, 7} };

    // ---- resident Whh split (w_hi ch 0-3, w_lo ch 4-7) + bhh cache ----
    for (int i = tid; i < 48 * 512; i += 256) {
        int c = i >> 9, k = i & 511;
        int gate = c >> 4, hc = c & 15;
        float v = Whh[(long)(gate * 512 + hcolBase + hc) * 512 + k];
        __nv_bfloat16 hi = __float2bfloat16(v);
        __nv_bfloat16 lo = __float2bfloat16(v - __bfloat162float(hi));
        int ch = k >> 7, off = k & 127;
        sW[ch * R2_WCH + c * R2_SAW + off]       = hi;
        sW[(ch + 4) * R2_WCH + c * R2_SAW + off] = lo;
    }
    if (tid < 48)
        sBH[tid] = bhh[(tid >> 4) * 512 + hcolBase + (tid & 15)];
    __syncthreads();

    // ---- prologue: prefetch gi(0) ----
    #pragma unroll
    for (int i = 0; i < 2; i++) {
        int f = i * 256 + tid;
        if (f < 384) {
            int r = f / 12, rest = f % 12, seg = rest >> 2, q = rest & 3;
            cp16(suGI + (uint32_t)(r * 48 + seg * 16 + q * 4) * 4,
                 gi_base + (long)(rowBase + r) * gi_bstride + seg * 512 + hcolBase + q * 4);
        }
    }
    CP_COMMIT();

    int* ctr = counters + mq;

    for (int t = 0; t < nsteps; t++) {
        const __nv_bfloat16* hcs = hcat + (t & 1) * 131072;
        __nv_bfloat16* hcd = hcat + ((t + 1) & 1) * 131072;

        // ---- group A: h_hi (4 chunks) ----
        #pragma unroll
        for (int i = 0; i < 8; i++) {
            int f = i * 256 + tid;
            int r = f >> 6, qq = f & 63;
            int hb = qq >> 4, off8 = (qq & 15) * 8;
            cp16(suH + (uint32_t)(hb * R2_HCH + r * R2_SAW + off8) * 2,
                 hcs + (long)(rowBase + r) * 1024 + qq * 8);
        }
        CP_COMMIT();

        // ---- group B: h_lo (4 chunks) ----
        #pragma unroll
        for (int i = 0; i < 8; i++) {
            int f = i * 256 + tid;
            int r = f >> 6, qq = f & 63;
            int hb = 4 + (qq >> 4), off8 = (qq & 15) * 8;
            cp16(suH + (uint32_t)(hb * R2_HCH + r * R2_SAW + off8) * 2,
                 hcs + (long)(rowBase + r) * 1024 + 512 + qq * 8);
        }
        CP_COMMIT();

        CP_WAIT1();              // gi(t) + group A complete
        __syncthreads();

        float acc[3][4];
        #pragma unroll
        for (int j = 0; j < 3; j++)
            #pragma unroll
            for (int q = 0; q < 4; q++) acc[j][q] = 0.f;

        // ---- phase 1: 4 h_hi chunks ----
        #pragma unroll
        for (int cc = 0; cc < 4; cc++) {
            const int c  = order[kg][cc];
            const int wb = (c < 4) ? c : c - 4;
            const int hb = (c < 8) ? c : c - 8;
            const uint32_t bA = suH + (uint32_t)hb * (R2_HCH * 2);
            const uint32_t bW = suW + (uint32_t)wb * (R2_WCH * 2);
            #pragma unroll
            for (int ks = 0; ks < 8; ks++) {
                uint32_t af[4], b0[4], b1[4];
                ldmx4(af, bA + 2u * (uint32_t)((wm + (lane & 15)) * R2_SAW + (lane >> 4) * 8 + ks * 16));
                ldmx4(b0, bW + 2u * (uint32_t)((wn +     (lane & 15)) * R2_SAW + (lane >> 4) * 8 + ks * 16));
                ldmx4(b1, bW + 2u * (uint32_t)((wn + 8 + (lane & 15)) * R2_SAW + (lane >> 4) * 8 + ks * 16));
                uint32_t f0[2] = { b0[0], b0[2] };
                uint32_t f1[2] = { b0[1], b0[3] };
                uint32_t f2[2] = { b1[1], b1[3] };
                mma16816(acc[0], af, f0);
                mma16816(acc[1], af, f1);
                mma16816(acc[2], af, f2);
            }
        }

        CP_WAIT0();              // group B complete
        __syncthreads();

        // ---- phase 2: 2 h_lo chunks ----
        #pragma unroll
        for (int cc = 4; cc < 6; cc++) {
            const int c  = order[kg][cc];
            const int wb = (c < 4) ? c : c - 4;
            const int hb = (c < 8) ? c : c - 8;
            const uint32_t bA = suH + (uint32_t)hb * (R2_HCH * 2);
            const uint32_t bW = suW + (uint32_t)wb * (R2_WCH * 2);
            #pragma unroll
            for (int ks = 0; ks < 8; ks++) {
                uint32_t af[4], b0[4], b1[4];
                ldmx4(af, bA + 2u * (uint32_t)((wm + (lane & 15)) * R2_SAW + (lane >> 4) * 8 + ks * 16));
                ldmx4(b0, bW + 2u * (uint32_t)((wn +     (lane & 15)) * R2_SAW + (lane >> 4) * 8 + ks * 16));
                ldmx4(b1, bW + 2u * (uint32_t)((wn + 8 + (lane & 15)) * R2_SAW + (lane >> 4) * 8 + ks * 16));
                uint32_t f0[2] = { b0[0], b0[2] };
                uint32_t f1[2] = { b0[1], b0[3] };
                uint32_t f2[2] = { b1[1], b1[3] };
                mma16816(acc[0], af, f0);
                mma16816(acc[1], af, f1);
                mma16816(acc[2], af, f2);
            }
        }

        // ---- write K-group partial gh tiles ----
        {
            float* dst = sGH + kg * (32 * 48);
            #pragma unroll
            for (int j = 0; j < 3; j++) {
                int col = wn + j * 8 + 2 * tq;
                *(float2*)(dst + (wm + g) * 48 + col)     = make_float2(acc[j][0], acc[j][1]);
                *(float2*)(dst + (wm + g + 8) * 48 + col) = make_float2(acc[j][2], acc[j][3]);
            }
        }
        __syncthreads();

        // ---- gate fusion: hpv reconstructed from smem h (hi+lo); store hcd now ----
        float hnv[2];
        __nv_bfloat16 hiv[2], lov[2];
        #pragma unroll
        for (int q2 = 0; q2 < 2; q2++) {
            int o   = q2 * 256 + tid;
            int row = o >> 4;
            int hc  = o & 15;
            int b   = rowBase + row;
            int col = hcolBase + hc;
            float ghr = sGH[row * 48 + hc]      + sGH[1536 + row * 48 + hc]      + sBH[hc];
            float ghz = sGH[row * 48 + 16 + hc] + sGH[1536 + row * 48 + 16 + hc] + sBH[16 + hc];
            float ghn = sGH[row * 48 + 32 + hc] + sGH[1536 + row * 48 + 32 + hc] + sBH[32 + hc];
            float gir = sGI[row * 48 + hc];
            float giz = sGI[row * 48 + 16 + hc];
            float gin = sGI[row * 48 + 32 + hc];
            float r  = 1.f / (1.f + expf(-(gir + ghr)));
            float z  = 1.f / (1.f + expf(-(giz + ghz)));
            float n  = tanhf(gin + r * ghn);
            int hb = col >> 7, off = col & 127;
            float hpv = __bfloat162float(sHbf[hb * R2_HCH + row * R2_SAW + off])
                      + __bfloat162float(sHbf[(hb + 4) * R2_HCH + row * R2_SAW + off]);
            float hn = (1.f - z) * n + z * hpv;
            __nv_bfloat16 hi = __float2bfloat16(hn);
            __nv_bfloat16 lo = __float2bfloat16(hn - __bfloat162float(hi));
            hcd[(long)b * 1024 + col]       = hi;
            hcd[(long)b * 1024 + 512 + col] = lo;
            hnv[q2] = hn; hiv[q2] = hi; lov[q2] = lo;
        }
        __syncthreads();         // hcd stores done CTA-wide; sGI/sH reads done

        // ---- early arrive (release orders hcd stores) ----
        if (tid == 0)
            asm volatile("red.release.gpu.global.add.u32 [%0], 1;" :: "l"(ctr) : "memory");

        // ---- deferred stores (overlap spin) ----
        #pragma unroll
        for (int q2 = 0; q2 < 2; q2++) {
            int o   = q2 * 256 + tid;
            int row = o >> 4;
            int hc  = o & 15;
            int b   = rowBase + row;
            int col = hcolBase + hc;
            if (y_out)
                y_out[(long)b * y_bstride + (long)t * y_tstride + col] = hnv[q2];
            if (ycat) {
                __nv_bfloat16* yr = ycat + ((long)b * nsteps + t) * 1536;
                yr[col]        = hiv[q2];
                yr[512 + col]  = lov[q2];
                yr[1024 + col] = hiv[q2];
            }
        }

        // ---- prefetch gi(t+1) (overlaps spin) ----
        {
            const int tn = t + 1;
            if (tn < nsteps) {
                const float* gi_n = gi_base + (long)tn * G3H;
                #pragma unroll
                for (int i = 0; i < 2; i++) {
                    int f = i * 256 + tid;
                    if (f < 384) {
                        int r = f / 12, rest = f % 12, seg = rest >> 2, q = rest & 3;
                        cp16(suGI + (uint32_t)(r * 48 + seg * 16 + q * 4) * 4,
                             gi_n + (long)(rowBase + r) * gi_bstride + seg * 512 + hcolBase + q * 4);
                    }
                }
            }
            CP_COMMIT();
        }

        // ---- late wait (acquire orders subsequent h loads) ----
        if (tid == 0) {
            int target = 32 * (t + 1);
            uint32_t v;
            while (1) {
                asm volatile("ld.acquire.gpu.global.u32 %0, [%1];" : "=r"(v) : "l"(ctr));
                if ((int)v >= target) break;
                __nanosleep(32);
            }
        }
        __syncthreads();
    }
}

// ================= small kernels =================
__global__ void gather_emb_cat(const int* __restrict__ ids, const float* __restrict__ emb,
                               __nv_bfloat16* __restrict__ tg)
{
    int m = blockIdx.x;
    int t = threadIdx.x;
    int id = ids[m];
    float x = emb[(long)id * E_ + t];
    __nv_bfloat16 hi = __float2bfloat16(x);
    __nv_bfloat16 lo = __float2bfloat16(x - __bfloat162float(hi));
    __nv_bfloat16* dst = tg + (long)m * (3 * E_);
    dst[t]           = hi;
    dst[E_ + t]      = lo;
    dst[2 * E_ + t]  = hi;
}

__global__ void pool_kernel(const float* __restrict__ y, const int* __restrict__ lengths,
                            float* __restrict__ pooled)
{
    int idx = blockIdx.x * blockDim.x + threadIdx.x;
    int b = idx >> 9, h = idx & 511;
    int L = lengths[b];
    float s = 0.f;
    for (int t = 0; t < L; t++) s += y[((long)b * T_ + t) * H_ + h];
    pooled[idx] = s;
}

__global__ void rowloss_kernel(const float* __restrict__ x, float* __restrict__ rowloss,
                               int ld)
{
    __shared__ float sh[V_];
    __shared__ float red[256];
    int b = blockIdx.x;
    int t = threadIdx.x;

    float mx = -1e30f;
    for (int v = t; v < V_; v += 256) {
        float s = 1.f / (1.f + expf(-x[(long)b * ld + v]));
        sh[v] = s;
        mx = fmaxf(mx, s);
    }
    red[t] = mx; __syncthreads();
    for (int o = 128; o > 0; o >>= 1) {
        if (t < o) red[t] = fmaxf(red[t], red[t + o]);
        __syncthreads();
    }
    mx = red[0];
    __syncthreads();

    float sum = 0.f;
    for (int v = t; v < V_; v += 256) sum += expf(sh[v] - mx);
    red[t] = sum; __syncthreads();
    for (int o = 128; o > 0; o >>= 1) {
        if (t < o) red[t] += red[t + o];
        __syncthreads();
    }
    if (t == 0) rowloss[b] = (mx + logf(red[0])) - sh[V_ - 1];
}

__global__ void finalize_kernel(const float* __restrict__ rowloss, float* __restrict__ out)
{
    __shared__ float red[128];
    int t = threadIdx.x;
    red[t] = rowloss[t]; __syncthreads();
    for (int o = 64; o > 0; o >>= 1) {
        if (t < o) red[t] += red[t + o];
        __syncthreads();
    }
    if (t == 0) out[0] = red[0] / 128.f;
}

// ================= host =================
static __nv_bfloat16 *s_Acat, *s_Wcat, *s_hcat;

static void gemm_full(const float* A, const float* W, const float* bias, float* C,
                      int M, int Nreal, int Npad, int K, int ldC)
{
    long ta = (long)M * K;
    conv_A<<<(unsigned)((ta + 255) / 256), 256>>>(A, s_Acat, K, ta);
    long tw = (long)Npad * K;
    conv_W<<<(unsigned)((tw + 255) / 256), 256>>>(W, s_Wcat, K, Nreal, tw);
    dim3 grid(Npad / 128, M / 128);
    mma_gemm<<<grid, 256, MMG_SMEM>>>(s_Acat, s_Wcat, bias, C, 3 * K, Nreal, ldC);
}

static void gemm_precat(const __nv_bfloat16* Acat, const float* W, const float* bias,
                        float* C, int M, int Nreal, int Npad, int K, int ldC)
{
    long tw = (long)Npad * K;
    conv_W<<<(unsigned)((tw + 255) / 256), 256>>>(W, s_Wcat, K, Nreal, tw);
    dim3 grid(Npad / 128, M / 128);
    mma_gemm<<<grid, 256, MMG_SMEM>>>(Acat, s_Wcat, bias, C, 3 * K, Nreal, ldC);
}

extern "C" void kernel_launch(void* const* d_in, const int* in_sizes, int n_in,
                              void* d_out, int out_size)
{
    const float* source    = (const float*)d_in[0];
    const int*   tgt_ids   = (const int*)  d_in[1];
    const int*   lengths   = (const int*)  d_in[2];
    const float* emb       = (const float*)d_in[3];
    const float* eWih0 = (const float*)d_in[4],  *eWhh0 = (const float*)d_in[5];
    const float* ebih0 = (const float*)d_in[6],  *ebhh0 = (const float*)d_in[7];
    const float* eWih1 = (const float*)d_in[8],  *eWhh1 = (const float*)d_in[9];
    const float* ebih1 = (const float*)d_in[10], *ebhh1 = (const float*)d_in[11];
    const float* dWih0 = (const float*)d_in[12], *dWhh0 = (const float*)d_in[13];
    const float* dbih0 = (const float*)d_in[14], *dbhh0 = (const float*)d_in[15];
    const float* dWih1 = (const float*)d_in[16], *dWhh1 = (const float*)d_in[17];
    const float* dbih1 = (const float*)d_in[18], *dbhh1 = (const float*)d_in[19];
    const float* fcW1 = (const float*)d_in[20], *fcb1 = (const float*)d_in[21];
    const float* fcW2 = (const float*)d_in[22], *fcb2 = (const float*)d_in[23];
    const float* fcW3 = (const float*)d_in[24], *fcb3 = (const float*)d_in[25];
    float* out = (float*)d_out;

    float *GI, *Yd1, *pooled, *F1, *F2, *F3, *rl;
    int* ctr;
    cudaGetSymbolAddress((void**)&GI,  g_GI);
    cudaGetSymbolAddress((void**)&Yd1, g_Yd1);
    cudaGetSymbolAddress((void**)&pooled, g_pooled);
    cudaGetSymbolAddress((void**)&F1,  g_F1);
    cudaGetSymbolAddress((void**)&F2,  g_F2);
    cudaGetSymbolAddress((void**)&F3,  g_F3);
    cudaGetSymbolAddress((void**)&rl,  g_rowloss);
    cudaGetSymbolAddress((void**)&ctr, g_ctr);
    cudaGetSymbolAddress((void**)&s_Acat, g_Acat);
    cudaGetSymbolAddress((void**)&s_Wcat, g_Wcat);
    cudaGetSymbolAddress((void**)&s_hcat, g_hcat);

    __nv_bfloat16* hc0 = s_hcat;                 // enc L0
    __nv_bfloat16* hc1 = s_hcat + 262144;        // enc L1
    __nv_bfloat16* hc2 = s_hcat + 524288;        // dec L0
    __nv_bfloat16* hc3 = s_hcat + 786432;        // dec L1

    cudaFuncSetAttribute(mma_gemm,
                         cudaFuncAttributeMaxDynamicSharedMemorySize, MMG_SMEM);
    cudaFuncSetAttribute(gru_layer_mma4,
                         cudaFuncAttributeMaxDynamicSharedMemorySize, R4_SMEM);

    cudaMemsetAsync(ctr, 0, 16 * sizeof(int), 0);
    cudaMemsetAsync(hc0, 0, 131072 * sizeof(__nv_bfloat16), 0);   // slot0 = h0 zeros
    cudaMemsetAsync(hc1, 0, 131072 * sizeof(__nv_bfloat16), 0);

    // ---- encoder layer 0 ----
    gemm_full(source, eWih0, ebih0, GI, B_ * S_, G3H, G3H, D_, G3H);
    gru_layer_mma4<<<128, 256, R4_SMEM>>>(
        GI, (long)S_ * G3H, eWhh0, ebhh0,
        hc0, (float*)0, 0, 0, s_Acat /*Y0 cat*/, S_, ctr + 0);
    // enc L0 final hcat is hc0 slot 0 (512 even) -> dec L0 initial
    cudaMemcpyAsync(hc2, hc0, 131072 * sizeof(__nv_bfloat16),
                    cudaMemcpyDeviceToDevice, 0);

    // ---- encoder layer 1 ----
    gemm_precat(s_Acat, eWih1, ebih1, GI, B_ * S_, G3H, G3H, H_, G3H);
    gru_layer_mma4<<<128, 256, R4_SMEM>>>(
        GI, (long)S_ * G3H, eWhh1, ebhh1,
        hc1, (float*)0, 0, 0, (__nv_bfloat16*)0, S_, ctr + 4);
    cudaMemcpyAsync(hc3, hc1, 131072 * sizeof(__nv_bfloat16),
                    cudaMemcpyDeviceToDevice, 0);

    // ---- decoder layer 0 ----
    gather_emb_cat<<<B_ * T_, 256>>>(tgt_ids, emb, s_Acat);
    gemm_precat(s_Acat, dWih0, dbih0, GI, B_ * T_, G3H, G3H, E_, G3H);
    gru_layer_mma4<<<128, 256, R4_SMEM>>>(
        GI, (long)T_ * G3H, dWhh0, dbhh0,
        hc2, (float*)0, 0, 0, s_Acat /*Yd0 cat*/, T_, ctr + 8);

    // ---- decoder layer 1 ----
    gemm_precat(s_Acat, dWih1, dbih1, GI, B_ * T_, G3H, G3H, H_, G3H);
    gru_layer_mma4<<<128, 256, R4_SMEM>>>(
        GI, (long)T_ * G3H, dWhh1, dbhh1,
        hc3, Yd1, (long)T_ * H_, (long)H_, (__nv_bfloat16*)0, T_, ctr + 12);

    // ---- pool + FC head + loss ----
    pool_kernel<<<256, 256>>>(Yd1, lengths, pooled);
    gemm_full(pooled, fcW1, fcb1, F1, B_, 5 * H_, 5 * H_, H_,     5 * H_);
    gemm_full(F1,     fcW2, fcb2, F2, B_, 2 * H_, 2 * H_, 5 * H_, 2 * H_);
    gemm_full(F2,     fcW3, fcb3, F3, B_, V_,     1024,   2 * H_, 1024);
    rowloss_kernel<<<B_, 256>>>(F3, rl, 1024);
    finalize_kernel<<<1, 128>>>(rl, out);
}

// round 14
// speedup vs baseline: 2.2610x; 1.0160x over previous
#include <cuda_runtime.h>
#include <cuda_bf16.h>
#include <math.h>
#include <stdint.h>

// ---------------- problem dims ----------------
#define B_   128
#define S_   512
#define D_   256
#define H_   512
#define E_   256
#define V_   1002
#define T_   34
#define G3H  1536   // 3*H

// ---------------- device scratch ----------------
__device__ float g_GI [100663296];              // 65536 * 1536
__device__ float g_Yd1[2228224];                // 4352 * 512 (fp32, for pooling)
__device__ float g_pooled[65536];
__device__ float g_F1 [327680];
__device__ float g_F2 [131072];
__device__ float g_F3 [131072];
__device__ float g_rowloss[128];
__device__ int   g_ctr[16];
__device__ __nv_bfloat16 g_Acat[100663296];     // A in (hi|lo|hi) cat form
__device__ __nv_bfloat16 g_Wcat[8388608];       // W in (hi|hi|lo) cat form
__device__ __nv_bfloat16 g_hcat[1048576];       // 4 layers x [2][128*1024] (hi|lo)

// ================= common PTX helpers =================
__device__ __forceinline__ uint32_t smem_u32(const void* p) {
    uint32_t a;
    asm("{ .reg .u64 t; cvta.to.shared.u64 t, %1; cvt.u32.u64 %0, t; }" : "=r"(a) : "l"(p));
    return a;
}
__device__ __forceinline__ void mma16816(float* c, const uint32_t* a, const uint32_t* b)
{
    asm volatile(
        "mma.sync.aligned.m16n8k16.row.col.f32.bf16.bf16.f32 "
        "{%0,%1,%2,%3}, {%4,%5,%6,%7}, {%8,%9}, {%0,%1,%2,%3};"
        : "+f"(c[0]), "+f"(c[1]), "+f"(c[2]), "+f"(c[3])
        : "r"(a[0]), "r"(a[1]), "r"(a[2]), "r"(a[3]), "r"(b[0]), "r"(b[1]));
}
__device__ __forceinline__ void ldmx4(uint32_t* r, uint32_t addr)
{
    asm volatile("ldmatrix.sync.aligned.m8n8.x4.shared.b16 {%0,%1,%2,%3}, [%4];"
        : "=r"(r[0]), "=r"(r[1]), "=r"(r[2]), "=r"(r[3]) : "r"(addr));
}
__device__ __forceinline__ void cp16(uint32_t dst, const void* src)
{
    asm volatile("cp.async.cg.shared.global [%0], [%1], 16;" :: "r"(dst), "l"(src));
}
#define CP_COMMIT() asm volatile("cp.async.commit_group;" ::: "memory")
#define CP_WAIT0()  asm volatile("cp.async.wait_group 0;" ::: "memory")
#define CP_WAIT1()  asm volatile("cp.async.wait_group 1;" ::: "memory")

// ================= MUFU-free transcendentals (FMA/ALU pipes only) =================
// exp(x) for |x| <= ~60: range-reduce via 2^23*1.5 add trick + deg-6 Taylor of 2^f.
__device__ __forceinline__ float exp_fma(float x)
{
    float y  = x * 1.4426950408889634f;            // x * log2(e)
    float kf = y + 12582912.0f;                    // round-to-nearest int in mantissa
    int   ik = __float_as_int(kf) - 0x4B400000;    // k
    float f  = y - (kf - 12582912.0f);             // f in [-0.5, 0.5]
    // 2^f Taylor: sum (ln2 f)^n / n!, n=0..6  (rel err ~1.2e-7 on [-0.5,0.5])
    float p = 1.5403530e-4f;
    p = fmaf(p, f, 1.3333558e-3f);
    p = fmaf(p, f, 9.6181291e-3f);
    p = fmaf(p, f, 5.5504109e-2f);
    p = fmaf(p, f, 2.4022651e-1f);
    p = fmaf(p, f, 6.9314718e-1f);
    p = fmaf(p, f, 1.0f);
    return __int_as_float(__float_as_int(p) + (ik << 23));
}
// 1/a for a in [1, ~1e30): bit-trick seed + 3 Newton (err ~4e-11)
__device__ __forceinline__ float rcp_fma(float a)
{
    float r = __int_as_float(0x7EF311C3 - __float_as_int(a));
    r = r * fmaf(-a, r, 2.0f);
    r = r * fmaf(-a, r, 2.0f);
    r = r * fmaf(-a, r, 2.0f);
    return r;
}
__device__ __forceinline__ float sigmoid_fma(float x)
{
    x = fminf(fmaxf(x, -30.f), 30.f);
    return rcp_fma(1.0f + exp_fma(-x));
}
__device__ __forceinline__ float tanh_fma(float x)
{
    x = fminf(fmaxf(x, -30.f), 30.f);
    float t = exp_fma(-2.0f * x);
    return (1.0f - t) * rcp_fma(1.0f + t);
}

// ================= fp32 -> bf16 split converters =================
__global__ void conv_A(const float* __restrict__ A, __nv_bfloat16* __restrict__ Ac,
                       int K, long total)
{
    long idx = (long)blockIdx.x * 256 + threadIdx.x;
    if (idx >= total) return;
    int row = (int)(idx / K);
    int col = (int)(idx % K);
    float x = A[idx];
    __nv_bfloat16 hi = __float2bfloat16(x);
    __nv_bfloat16 lo = __float2bfloat16(x - __bfloat162float(hi));
    long base = (long)row * 3 * K;
    Ac[base + col]         = hi;
    Ac[base + K + col]     = lo;
    Ac[base + 2 * K + col] = hi;
}

__global__ void conv_W(const float* __restrict__ W, __nv_bfloat16* __restrict__ Wc,
                       int K, int Nreal, long total)
{
    long idx = (long)blockIdx.x * 256 + threadIdx.x;
    if (idx >= total) return;
    int n = (int)(idx / K);
    int c = (int)(idx % K);
    float x = (n < Nreal) ? W[(long)n * K + c] : 0.f;
    __nv_bfloat16 hi = __float2bfloat16(x);
    __nv_bfloat16 lo = __float2bfloat16(x - __bfloat162float(hi));
    long base = (long)n * 3 * K;
    Wc[base + c]         = hi;
    Wc[base + K + c]     = hi;
    Wc[base + 2 * K + c] = lo;
}

// ================= mma.sync bf16 GEMM (single-sync mainloop, R13-proven) =================
#define STAGES    3
#define MMG_SAW   72
#define MMG_TILE  (128 * MMG_SAW)
#define MMG_SMEM  (STAGES * 2 * MMG_TILE * 2)

__global__ __launch_bounds__(256) void mma_gemm(
    const __nv_bfloat16* __restrict__ A, const __nv_bfloat16* __restrict__ Wc,
    const float* __restrict__ bias, float* __restrict__ C,
    int Kext, int Nreal, int ldC)
{
    extern __shared__ __nv_bfloat16 sm[];
    const uint32_t suA = smem_u32(sm);
    const uint32_t suB = suA + STAGES * MMG_TILE * 2;

    const int tid  = threadIdx.x;
    const int wid  = tid >> 5;
    const int lane = tid & 31;
    const int g    = lane >> 2;
    const int t    = lane & 3;
    const int wm   = (wid & 3) * 32;
    const int wn   = (wid >> 2) * 64;
    const int m0   = blockIdx.y * 128;
    const int n0   = blockIdx.x * 128;

    const int aoff = (wm + (lane & 15)) * MMG_SAW + (lane >> 4) * 8;
    const int boff = (wn + (lane & 15)) * MMG_SAW + (lane >> 4) * 8;

    float acc[2][8][4];
    #pragma unroll
    for (int i = 0; i < 2; i++)
        #pragma unroll
        for (int j = 0; j < 8; j++)
            #pragma unroll
            for (int q = 0; q < 4; q++) acc[i][j][q] = 0.f;

    const int nk = Kext >> 6;

    #pragma unroll
    for (int s = 0; s < STAGES - 1; s++) {
        if (s < nk) {
            const int k0 = s << 6;
            const uint32_t dA = suA + s * (MMG_TILE * 2);
            const uint32_t dB = suB + s * (MMG_TILE * 2);
            #pragma unroll
            for (int i = 0; i < 4; i++) {
                int f = i * 256 + tid;
                int r = f >> 3, u = (f & 7) * 8;
                cp16(dA + (uint32_t)(r * MMG_SAW + u) * 2, A  + (long)(m0 + r) * Kext + k0 + u);
                cp16(dB + (uint32_t)(r * MMG_SAW + u) * 2, Wc + (long)(n0 + r) * Kext + k0 + u);
            }
        }
        CP_COMMIT();
    }

    for (int kc = 0; kc < nk; kc++) {
        CP_WAIT1();
        __syncthreads();

        {
            const int kl = kc + 2;
            if (kl < nk) {
                const int k0 = kl << 6;
                const int bfi = kl % STAGES;
                const uint32_t dA = suA + bfi * (MMG_TILE * 2);
                const uint32_t dB = suB + bfi * (MMG_TILE * 2);
                #pragma unroll
                for (int i = 0; i < 4; i++) {
                    int f = i * 256 + tid;
                    int r = f >> 3, u = (f & 7) * 8;
                    cp16(dA + (uint32_t)(r * MMG_SAW + u) * 2, A  + (long)(m0 + r) * Kext + k0 + u);
                    cp16(dB + (uint32_t)(r * MMG_SAW + u) * 2, Wc + (long)(n0 + r) * Kext + k0 + u);
                }
            }
            CP_COMMIT();
        }

        const int p = kc % STAGES;
        const uint32_t bA = suA + p * (MMG_TILE * 2);
        const uint32_t bB = suB + p * (MMG_TILE * 2);

        #pragma unroll
        for (int ks = 0; ks < 4; ks++) {
            uint32_t af[2][4], bf[4][4];
            #pragma unroll
            for (int i = 0; i < 2; i++)
                ldmx4(af[i], bA + 2u * (uint32_t)(aoff + i * 16 * MMG_SAW + ks * 16));
            #pragma unroll
            for (int j = 0; j < 4; j++)
                ldmx4(bf[j], bB + 2u * (uint32_t)(boff + j * 16 * MMG_SAW + ks * 16));
            #pragma unroll
            for (int i = 0; i < 2; i++)
                #pragma unroll
                for (int jj = 0; jj < 8; jj++) {
                    uint32_t b2[2] = { bf[jj >> 1][jj & 1], bf[jj >> 1][(jj & 1) + 2] };
                    mma16816(acc[i][jj], af[i], b2);
                }
        }
    }

    #pragma unroll
    for (int i = 0; i < 2; i++) {
        #pragma unroll
        for (int j = 0; j < 8; j++) {
            int col = n0 + wn + j * 8 + 2 * t;
            if (col >= Nreal) continue;
            float b0 = bias[col], b1 = bias[col + 1];
            int row0 = m0 + wm + i * 16 + g;
            float2 v0 = make_float2(acc[i][j][0] + b0, acc[i][j][1] + b1);
            float2 v1 = make_float2(acc[i][j][2] + b0, acc[i][j][3] + b1);
            *(float2*)(C + (long)row0 * ldC + col)       = v0;
            *(float2*)(C + (long)(row0 + 8) * ldC + col) = v1;
        }
    }
}

// ================= persistent tensor-core GRU layer, v5 =================
// v4 with the gate fusion moved entirely off MUFU (FMA-pipe exp/rcp).
#define R2_SAW  136
#define R2_WCH  (48 * R2_SAW)
#define R2_HCH  (32 * R2_SAW)
#define R4_OFFH  (8 * R2_WCH * 2)               // 104448
#define R4_OFFGH (R4_OFFH + 8 * R2_HCH * 2)     // 174080
#define R4_OFFGI (R4_OFFGH + 2 * 32 * 48 * 4)   // 186368
#define R4_OFFBH (R4_OFFGI + 32 * 48 * 4)       // 192512
#define R4_SMEM  (R4_OFFBH + 48 * 4)            // 192704

__global__ __launch_bounds__(256) void gru_layer_mma5(
    const float* __restrict__ gi_base, long gi_bstride,
    const float* __restrict__ Whh, const float* __restrict__ bhh,
    __nv_bfloat16* __restrict__ hcat,       // [2][128*1024], slot 0 prefilled (h0)
    float* __restrict__ y_out, long y_bstride, long y_tstride,
    __nv_bfloat16* __restrict__ ycat,       // optional (hi|lo|hi) rows, row = b*nsteps+t
    int nsteps, int* counters)
{
    extern __shared__ char smx[];
    __nv_bfloat16* sW = (__nv_bfloat16*)smx;
    const __nv_bfloat16* sHbf = (const __nv_bfloat16*)(smx + R4_OFFH);
    float* sGH = (float*)(smx + R4_OFFGH);
    float* sGI = (float*)(smx + R4_OFFGI);
    float* sBH = (float*)(smx + R4_OFFBH);
    const uint32_t suW  = smem_u32(smx);
    const uint32_t suH  = suW + R4_OFFH;
    const uint32_t suGI = suW + R4_OFFGI;

    const int tid  = threadIdx.x;
    const int wid  = tid >> 5;
    const int lane = tid & 31;
    const int g    = lane >> 2;
    const int tq   = lane & 3;
    const int nt   = blockIdx.x & 31;
    const int mq   = blockIdx.x >> 5;
    const int hcolBase = nt * 16;
    const int rowBase  = mq * 32;
    const int wm = (wid & 1) * 16;
    const int wn = ((wid >> 1) & 1) * 24;
    const int kg = wid >> 2;

    const int order[2][6] = { {0, 1, 2, 3, 4, 5}, {8, 9, 10, 11, 6, 7} };

    // ---- resident Whh split (w_hi ch 0-3, w_lo ch 4-7) + bhh cache ----
    for (int i = tid; i < 48 * 512; i += 256) {
        int c = i >> 9, k = i & 511;
        int gate = c >> 4, hc = c & 15;
        float v = Whh[(long)(gate * 512 + hcolBase + hc) * 512 + k];
        __nv_bfloat16 hi = __float2bfloat16(v);
        __nv_bfloat16 lo = __float2bfloat16(v - __bfloat162float(hi));
        int ch = k >> 7, off = k & 127;
        sW[ch * R2_WCH + c * R2_SAW + off]       = hi;
        sW[(ch + 4) * R2_WCH + c * R2_SAW + off] = lo;
    }
    if (tid < 48)
        sBH[tid] = bhh[(tid >> 4) * 512 + hcolBase + (tid & 15)];
    __syncthreads();

    // ---- prologue: prefetch gi(0) ----
    #pragma unroll
    for (int i = 0; i < 2; i++) {
        int f = i * 256 + tid;
        if (f < 384) {
            int r = f / 12, rest = f % 12, seg = rest >> 2, q = rest & 3;
            cp16(suGI + (uint32_t)(r * 48 + seg * 16 + q * 4) * 4,
                 gi_base + (long)(rowBase + r) * gi_bstride + seg * 512 + hcolBase + q * 4);
        }
    }
    CP_COMMIT();

    int* ctr = counters + mq;

    for (int t = 0; t < nsteps; t++) {
        const __nv_bfloat16* hcs = hcat + (t & 1) * 131072;
        __nv_bfloat16* hcd = hcat + ((t + 1) & 1) * 131072;

        // ---- group A: h_hi (4 chunks) ----
        #pragma unroll
        for (int i = 0; i < 8; i++) {
            int f = i * 256 + tid;
            int r = f >> 6, qq = f & 63;
            int hb = qq >> 4, off8 = (qq & 15) * 8;
            cp16(suH + (uint32_t)(hb * R2_HCH + r * R2_SAW + off8) * 2,
                 hcs + (long)(rowBase + r) * 1024 + qq * 8);
        }
        CP_COMMIT();

        // ---- group B: h_lo (4 chunks) ----
        #pragma unroll
        for (int i = 0; i < 8; i++) {
            int f = i * 256 + tid;
            int r = f >> 6, qq = f & 63;
            int hb = 4 + (qq >> 4), off8 = (qq & 15) * 8;
            cp16(suH + (uint32_t)(hb * R2_HCH + r * R2_SAW + off8) * 2,
                 hcs + (long)(rowBase + r) * 1024 + 512 + qq * 8);
        }
        CP_COMMIT();

        CP_WAIT1();              // gi(t) + group A complete
        __syncthreads();

        float acc[3][4];
        #pragma unroll
        for (int j = 0; j < 3; j++)
            #pragma unroll
            for (int q = 0; q < 4; q++) acc[j][q] = 0.f;

        // ---- phase 1: 4 h_hi chunks ----
        #pragma unroll
        for (int cc = 0; cc < 4; cc++) {
            const int c  = order[kg][cc];
            const int wb = (c < 4) ? c : c - 4;
            const int hb = (c < 8) ? c : c - 8;
            const uint32_t bA = suH + (uint32_t)hb * (R2_HCH * 2);
            const uint32_t bW = suW + (uint32_t)wb * (R2_WCH * 2);
            #pragma unroll
            for (int ks = 0; ks < 8; ks++) {
                uint32_t af[4], b0[4], b1[4];
                ldmx4(af, bA + 2u * (uint32_t)((wm + (lane & 15)) * R2_SAW + (lane >> 4) * 8 + ks * 16));
                ldmx4(b0, bW + 2u * (uint32_t)((wn +     (lane & 15)) * R2_SAW + (lane >> 4) * 8 + ks * 16));
                ldmx4(b1, bW + 2u * (uint32_t)((wn + 8 + (lane & 15)) * R2_SAW + (lane >> 4) * 8 + ks * 16));
                uint32_t f0[2] = { b0[0], b0[2] };
                uint32_t f1[2] = { b0[1], b0[3] };
                uint32_t f2[2] = { b1[1], b1[3] };
                mma16816(acc[0], af, f0);
                mma16816(acc[1], af, f1);
                mma16816(acc[2], af, f2);
            }
        }

        CP_WAIT0();              // group B complete
        __syncthreads();

        // ---- phase 2: 2 h_lo chunks ----
        #pragma unroll
        for (int cc = 4; cc < 6; cc++) {
            const int c  = order[kg][cc];
            const int wb = (c < 4) ? c : c - 4;
            const int hb = (c < 8) ? c : c - 8;
            const uint32_t bA = suH + (uint32_t)hb * (R2_HCH * 2);
            const uint32_t bW = suW + (uint32_t)wb * (R2_WCH * 2);
            #pragma unroll
            for (int ks = 0; ks < 8; ks++) {
                uint32_t af[4], b0[4], b1[4];
                ldmx4(af, bA + 2u * (uint32_t)((wm + (lane & 15)) * R2_SAW + (lane >> 4) * 8 + ks * 16));
                ldmx4(b0, bW + 2u * (uint32_t)((wn +     (lane & 15)) * R2_SAW + (lane >> 4) * 8 + ks * 16));
                ldmx4(b1, bW + 2u * (uint32_t)((wn + 8 + (lane & 15)) * R2_SAW + (lane >> 4) * 8 + ks * 16));
                uint32_t f0[2] = { b0[0], b0[2] };
                uint32_t f1[2] = { b0[1], b0[3] };
                uint32_t f2[2] = { b1[1], b1[3] };
                mma16816(acc[0], af, f0);
                mma16816(acc[1], af, f1);
                mma16816(acc[2], af, f2);
            }
        }

        // ---- write K-group partial gh tiles ----
        {
            float* dst = sGH + kg * (32 * 48);
            #pragma unroll
            for (int j = 0; j < 3; j++) {
                int col = wn + j * 8 + 2 * tq;
                *(float2*)(dst + (wm + g) * 48 + col)     = make_float2(acc[j][0], acc[j][1]);
                *(float2*)(dst + (wm + g + 8) * 48 + col) = make_float2(acc[j][2], acc[j][3]);
            }
        }
        __syncthreads();

        // ---- gate fusion (MUFU-free) ----
        float hnv[2];
        __nv_bfloat16 hiv[2], lov[2];
        #pragma unroll
        for (int q2 = 0; q2 < 2; q2++) {
            int o   = q2 * 256 + tid;
            int row = o >> 4;
            int hc  = o & 15;
            int b   = rowBase + row;
            int col = hcolBase + hc;
            float ghr = sGH[row * 48 + hc]      + sGH[1536 + row * 48 + hc]      + sBH[hc];
            float ghz = sGH[row * 48 + 16 + hc] + sGH[1536 + row * 48 + 16 + hc] + sBH[16 + hc];
            float ghn = sGH[row * 48 + 32 + hc] + sGH[1536 + row * 48 + 32 + hc] + sBH[32 + hc];
            float gir = sGI[row * 48 + hc];
            float giz = sGI[row * 48 + 16 + hc];
            float gin = sGI[row * 48 + 32 + hc];
            float r  = sigmoid_fma(gir + ghr);
            float z  = sigmoid_fma(giz + ghz);
            float n  = tanh_fma(gin + r * ghn);
            int hb = col >> 7, off = col & 127;
            float hpv = __bfloat162float(sHbf[hb * R2_HCH + row * R2_SAW + off])
                      + __bfloat162float(sHbf[(hb + 4) * R2_HCH + row * R2_SAW + off]);
            float hn = (1.f - z) * n + z * hpv;
            __nv_bfloat16 hi = __float2bfloat16(hn);
            __nv_bfloat16 lo = __float2bfloat16(hn - __bfloat162float(hi));
            hcd[(long)b * 1024 + col]       = hi;
            hcd[(long)b * 1024 + 512 + col] = lo;
            hnv[q2] = hn; hiv[q2] = hi; lov[q2] = lo;
        }
        __syncthreads();

        // ---- early arrive (release orders hcd stores) ----
        if (tid == 0)
            asm volatile("red.release.gpu.global.add.u32 [%0], 1;" :: "l"(ctr) : "memory");

        // ---- deferred stores (overlap spin) ----
        #pragma unroll
        for (int q2 = 0; q2 < 2; q2++) {
            int o   = q2 * 256 + tid;
            int row = o >> 4;
            int hc  = o & 15;
            int b   = rowBase + row;
            int col = hcolBase + hc;
            if (y_out)
                y_out[(long)b * y_bstride + (long)t * y_tstride + col] = hnv[q2];
            if (ycat) {
                __nv_bfloat16* yr = ycat + ((long)b * nsteps + t) * 1536;
                yr[col]        = hiv[q2];
                yr[512 + col]  = lov[q2];
                yr[1024 + col] = hiv[q2];
            }
        }

        // ---- prefetch gi(t+1) (overlaps spin) ----
        {
            const int tn = t + 1;
            if (tn < nsteps) {
                const float* gi_n = gi_base + (long)tn * G3H;
                #pragma unroll
                for (int i = 0; i < 2; i++) {
                    int f = i * 256 + tid;
                    if (f < 384) {
                        int r = f / 12, rest = f % 12, seg = rest >> 2, q = rest & 3;
                        cp16(suGI + (uint32_t)(r * 48 + seg * 16 + q * 4) * 4,
                             gi_n + (long)(rowBase + r) * gi_bstride + seg * 512 + hcolBase + q * 4);
                    }
                }
            }
            CP_COMMIT();
        }

        // ---- late wait (acquire) ----
        if (tid == 0) {
            int target = 32 * (t + 1);
            uint32_t v;
            while (1) {
                asm volatile("ld.acquire.gpu.global.u32 %0, [%1];" : "=r"(v) : "l"(ctr));
                if ((int)v >= target) break;
                __nanosleep(32);
            }
        }
        __syncthreads();
    }
}

// ================= small kernels =================
__global__ void gather_emb_cat(const int* __restrict__ ids, const float* __restrict__ emb,
                               __nv_bfloat16* __restrict__ tg)
{
    int m = blockIdx.x;
    int t = threadIdx.x;
    int id = ids[m];
    float x = emb[(long)id * E_ + t];
    __nv_bfloat16 hi = __float2bfloat16(x);
    __nv_bfloat16 lo = __float2bfloat16(x - __bfloat162float(hi));
    __nv_bfloat16* dst = tg + (long)m * (3 * E_);
    dst[t]           = hi;
    dst[E_ + t]      = lo;
    dst[2 * E_ + t]  = hi;
}

__global__ void pool_kernel(const float* __restrict__ y, const int* __restrict__ lengths,
                            float* __restrict__ pooled)
{
    int idx = blockIdx.x * blockDim.x + threadIdx.x;
    int b = idx >> 9, h = idx & 511;
    int L = lengths[b];
    float s = 0.f;
    for (int t = 0; t < L; t++) s += y[((long)b * T_ + t) * H_ + h];
    pooled[idx] = s;
}

__global__ void rowloss_kernel(const float* __restrict__ x, float* __restrict__ rowloss,
                               int ld)
{
    __shared__ float sh[V_];
    __shared__ float red[256];
    int b = blockIdx.x;
    int t = threadIdx.x;

    float mx = -1e30f;
    for (int v = t; v < V_; v += 256) {
        float s = 1.f / (1.f + expf(-x[(long)b * ld + v]));
        sh[v] = s;
        mx = fmaxf(mx, s);
    }
    red[t] = mx; __syncthreads();
    for (int o = 128; o > 0; o >>= 1) {
        if (t < o) red[t] = fmaxf(red[t], red[t + o]);
        __syncthreads();
    }
    mx = red[0];
    __syncthreads();

    float sum = 0.f;
    for (int v = t; v < V_; v += 256) sum += expf(sh[v] - mx);
    red[t] = sum; __syncthreads();
    for (int o = 128; o > 0; o >>= 1) {
        if (t < o) red[t] += red[t + o];
        __syncthreads();
    }
    if (t == 0) rowloss[b] = (mx + logf(red[0])) - sh[V_ - 1];
}

__global__ void finalize_kernel(const float* __restrict__ rowloss, float* __restrict__ out)
{
    __shared__ float red[128];
    int t = threadIdx.x;
    red[t] = rowloss[t]; __syncthreads();
    for (int o = 64; o > 0; o >>= 1) {
        if (t < o) red[t] += red[t + o];
        __syncthreads();
    }
    if (t == 0) out[0] = red[0] / 128.f;
}

// ================= host =================
static __nv_bfloat16 *s_Acat, *s_Wcat, *s_hcat;

static void gemm_full(const float* A, const float* W, const float* bias, float* C,
                      int M, int Nreal, int Npad, int K, int ldC)
{
    long ta = (long)M * K;
    conv_A<<<(unsigned)((ta + 255) / 256), 256>>>(A, s_Acat, K, ta);
    long tw = (long)Npad * K;
    conv_W<<<(unsigned)((tw + 255) / 256), 256>>>(W, s_Wcat, K, Nreal, tw);
    dim3 grid(Npad / 128, M / 128);
    mma_gemm<<<grid, 256, MMG_SMEM>>>(s_Acat, s_Wcat, bias, C, 3 * K, Nreal, ldC);
}

static void gemm_precat(const __nv_bfloat16* Acat, const float* W, const float* bias,
                        float* C, int M, int Nreal, int Npad, int K, int ldC)
{
    long tw = (long)Npad * K;
    conv_W<<<(unsigned)((tw + 255) / 256), 256>>>(W, s_Wcat, K, Nreal, tw);
    dim3 grid(Npad / 128, M / 128);
    mma_gemm<<<grid, 256, MMG_SMEM>>>(Acat, s_Wcat, bias, C, 3 * K, Nreal, ldC);
}

extern "C" void kernel_launch(void* const* d_in, const int* in_sizes, int n_in,
                              void* d_out, int out_size)
{
    const float* source    = (const float*)d_in[0];
    const int*   tgt_ids   = (const int*)  d_in[1];
    const int*   lengths   = (const int*)  d_in[2];
    const float* emb       = (const float*)d_in[3];
    const float* eWih0 = (const float*)d_in[4],  *eWhh0 = (const float*)d_in[5];
    const float* ebih0 = (const float*)d_in[6],  *ebhh0 = (const float*)d_in[7];
    const float* eWih1 = (const float*)d_in[8],  *eWhh1 = (const float*)d_in[9];
    const float* ebih1 = (const float*)d_in[10], *ebhh1 = (const float*)d_in[11];
    const float* dWih0 = (const float*)d_in[12], *dWhh0 = (const float*)d_in[13];
    const float* dbih0 = (const float*)d_in[14], *dbhh0 = (const float*)d_in[15];
    const float* dWih1 = (const float*)d_in[16], *dWhh1 = (const float*)d_in[17];
    const float* dbih1 = (const float*)d_in[18], *dbhh1 = (const float*)d_in[19];
    const float* fcW1 = (const float*)d_in[20], *fcb1 = (const float*)d_in[21];
    const float* fcW2 = (const float*)d_in[22], *fcb2 = (const float*)d_in[23];
    const float* fcW3 = (const float*)d_in[24], *fcb3 = (const float*)d_in[25];
    float* out = (float*)d_out;

    float *GI, *Yd1, *pooled, *F1, *F2, *F3, *rl;
    int* ctr;
    cudaGetSymbolAddress((void**)&GI,  g_GI);
    cudaGetSymbolAddress((void**)&Yd1, g_Yd1);
    cudaGetSymbolAddress((void**)&pooled, g_pooled);
    cudaGetSymbolAddress((void**)&F1,  g_F1);
    cudaGetSymbolAddress((void**)&F2,  g_F2);
    cudaGetSymbolAddress((void**)&F3,  g_F3);
    cudaGetSymbolAddress((void**)&rl,  g_rowloss);
    cudaGetSymbolAddress((void**)&ctr, g_ctr);
    cudaGetSymbolAddress((void**)&s_Acat, g_Acat);
    cudaGetSymbolAddress((void**)&s_Wcat, g_Wcat);
    cudaGetSymbolAddress((void**)&s_hcat, g_hcat);

    __nv_bfloat16* hc0 = s_hcat;                 // enc L0
    __nv_bfloat16* hc1 = s_hcat + 262144;        // enc L1
    __nv_bfloat16* hc2 = s_hcat + 524288;        // dec L0
    __nv_bfloat16* hc3 = s_hcat + 786432;        // dec L1

    cudaFuncSetAttribute(mma_gemm,
                         cudaFuncAttributeMaxDynamicSharedMemorySize, MMG_SMEM);
    cudaFuncSetAttribute(gru_layer_mma5,
                         cudaFuncAttributeMaxDynamicSharedMemorySize, R4_SMEM);

    cudaMemsetAsync(ctr, 0, 16 * sizeof(int), 0);
    cudaMemsetAsync(hc0, 0, 131072 * sizeof(__nv_bfloat16), 0);
    cudaMemsetAsync(hc1, 0, 131072 * sizeof(__nv_bfloat16), 0);

    // ---- encoder layer 0 ----
    gemm_full(source, eWih0, ebih0, GI, B_ * S_, G3H, G3H, D_, G3H);
    gru_layer_mma5<<<128, 256, R4_SMEM>>>(
        GI, (long)S_ * G3H, eWhh0, ebhh0,
        hc0, (float*)0, 0, 0, s_Acat /*Y0 cat*/, S_, ctr + 0);
    cudaMemcpyAsync(hc2, hc0, 131072 * sizeof(__nv_bfloat16),
                    cudaMemcpyDeviceToDevice, 0);

    // ---- encoder layer 1 ----
    gemm_precat(s_Acat, eWih1, ebih1, GI, B_ * S_, G3H, G3H, H_, G3H);
    gru_layer_mma5<<<128, 256, R4_SMEM>>>(
        GI, (long)S_ * G3H, eWhh1, ebhh1,
        hc1, (float*)0, 0, 0, (__nv_bfloat16*)0, S_, ctr + 4);
    cudaMemcpyAsync(hc3, hc1, 131072 * sizeof(__nv_bfloat16),
                    cudaMemcpyDeviceToDevice, 0);

    // ---- decoder layer 0 ----
    gather_emb_cat<<<B_ * T_, 256>>>(tgt_ids, emb, s_Acat);
    gemm_precat(s_Acat, dWih0, dbih0, GI, B_ * T_, G3H, G3H, E_, G3H);
    gru_layer_mma5<<<128, 256, R4_SMEM>>>(
        GI, (long)T_ * G3H, dWhh0, dbhh0,
        hc2, (float*)0, 0, 0, s_Acat /*Yd0 cat*/, T_, ctr + 8);

    // ---- decoder layer 1 ----
    gemm_precat(s_Acat, dWih1, dbih1, GI, B_ * T_, G3H, G3H, H_, G3H);
    gru_layer_mma5<<<128, 256, R4_SMEM>>>(
        GI, (long)T_ * G3H, dWhh1, dbhh1,
        hc3, Yd1, (long)T_ * H_, (long)H_, (__nv_bfloat16*)0, T_, ctr + 12);

    // ---- pool + FC head + loss ----
    pool_kernel<<<256, 256>>>(Yd1, lengths, pooled);
    gemm_full(pooled, fcW1, fcb1, F1, B_, 5 * H_, 5 * H_, H_,     5 * H_);
    gemm_full(F1,     fcW2, fcb2, F2, B_, 2 * H_, 2 * H_, 5 * H_, 2 * H_);
    gemm_full(F2,     fcW3, fcb3, F3, B_, V_,     1024,   2 * H_, 1024);
    rowloss_kernel<<<B_, 256>>>(F3, rl, 1024);
    finalize_kernel<<<1, 128>>>(rl, out);
}